// round 2
// baseline (speedup 1.0000x reference)
#include <cuda_runtime.h>
#include <cuda_bf16.h>

typedef unsigned long long ull;

#define F_IN   512
#define D_EMB  128
#define D_HID  64
#define N_CLS  32
#define MAXN   100000
#define MAXE   1600000

// ---------------- device scratch (no allocation allowed) ----------------
__device__ float g_bufA[MAXN * D_HID];
__device__ float g_bufB[MAXN * D_HID];
__device__ int   g_deg [MAXN + 2];
__device__ int   g_incl[MAXN + 2];
__device__ int   g_bsum[512];
__device__ int   g_rp  [MAXN + 2];
__device__ int   g_cur [MAXN + 2];
__device__ int   g_col [MAXE + 2];
__device__ float g_stats[256];
__device__ float g_part[256 * 64];

// ---------------- f32x2 packed-FMA helpers ----------------
__device__ __forceinline__ ull dup2(float v) {
    ull r; asm("mov.b64 %0, {%1, %1};" : "=l"(r) : "f"(v)); return r;
}
__device__ __forceinline__ void ffma2(ull &acc, ull a, ull b) {
    asm("fma.rn.f32x2 %0, %1, %2, %0;" : "+l"(acc) : "l"(a), "l"(b));
}
__device__ __forceinline__ float2 unpack2(ull v) {
    float2 r; asm("mov.b64 {%0, %1}, %2;" : "=f"(r.x), "=f"(r.y) : "l"(v)); return r;
}

// =====================================================================
// K1: g1 = relu(x @ W1 + b1) @ Wc1      [n x 64]
// BM=128 rows, BN=128 (=D_EMB), BK=32.  256 threads, 8x8 micro-tile,
// accumulators packed as f32x2 row-pairs.  Epilogue multiplies by Wc1
// from smem so h0 never hits HBM.
// =====================================================================
#define LIN1_HSS 132   // padded Hs row stride (floats), 16B-aligned
#define LIN1_SMEM ((D_EMB*D_HID + 128*LIN1_HSS) * 4)   // Wc1 + max(As+Bs,Hs)

__device__ __forceinline__ void l1_fetchA(const float* __restrict__ x, int n,
                                          int row0, int k0, int tid, float4* pa) {
    int m = tid & 127, cc = tid >> 7;
    const float4* p = (const float4*)(x + (size_t)(row0 + m) * F_IN + k0 + cc * 16);
    bool v = (row0 + m) < n;
#pragma unroll
    for (int i = 0; i < 4; i++)
        pa[i] = v ? p[i] : make_float4(0.f, 0.f, 0.f, 0.f);
}
__device__ __forceinline__ void l1_storeA(float* As, int tid, const float4* pa) {
    int m = tid & 127, cc = tid >> 7;
#pragma unroll
    for (int i = 0; i < 4; i++) {
        int kk = cc * 16 + i * 4;
        As[(kk + 0) * 128 + m] = pa[i].x;
        As[(kk + 1) * 128 + m] = pa[i].y;
        As[(kk + 2) * 128 + m] = pa[i].z;
        As[(kk + 3) * 128 + m] = pa[i].w;
    }
}
__device__ __forceinline__ void l1_fetchB(const float* __restrict__ W1,
                                          int k0, int tid, float4* pb) {
    const float4* p = (const float4*)(W1 + (size_t)k0 * D_EMB);
#pragma unroll
    for (int i = 0; i < 4; i++) pb[i] = p[tid + i * 256];
}
__device__ __forceinline__ void l1_storeB(float* Bs, int tid, const float4* pb) {
#pragma unroll
    for (int i = 0; i < 4; i++) ((float4*)Bs)[tid + i * 256] = pb[i];
}

__global__ void __launch_bounds__(256) k_lin1(
    const float* __restrict__ x, const float* __restrict__ W1,
    const float* __restrict__ b1, const float* __restrict__ Wc1,
    float* __restrict__ g1, int n)
{
    extern __shared__ float smem[];
    float* WcS = smem;                       // 128*64
    float* As  = smem + D_EMB * D_HID;       // 32*128
    float* Bs  = As + 32 * 128;              // 32*128
    float* Hs  = smem + D_EMB * D_HID;       // 128*132 (overlaps As/Bs)

    const int tid = threadIdx.x;
    const int tx = tid & 15, ty = tid >> 4;
    const int row0 = blockIdx.x * 128;

    // load Wc1 (128x64) into smem
    {
        const float4* s = (const float4*)Wc1;
        float4* d = (float4*)WcS;
#pragma unroll
        for (int i = 0; i < 8; i++) d[tid + i * 256] = s[tid + i * 256];
    }

    ull acc[4][8];
#pragma unroll
    for (int p = 0; p < 4; p++)
#pragma unroll
        for (int j = 0; j < 8; j++) acc[p][j] = 0ull;

    float4 pa[4], pb[4];
    l1_fetchA(x, n, row0, 0, tid, pa);
    l1_fetchB(W1, 0, tid, pb);
    l1_storeA(As, tid, pa);
    l1_storeB(Bs, tid, pb);
    __syncthreads();

    for (int kt = 0; kt < F_IN / 32; kt++) {
        if (kt + 1 < F_IN / 32) {
            l1_fetchA(x, n, row0, (kt + 1) * 32, tid, pa);
            l1_fetchB(W1, (kt + 1) * 32, tid, pb);
        }
#pragma unroll 8
        for (int kk = 0; kk < 32; kk++) {
            const double2 a01 = *(const double2*)(As + kk * 128 + ty * 8);
            const double2 a23 = *(const double2*)(As + kk * 128 + ty * 8 + 4);
            const float4  bl  = *(const float4*) (Bs + kk * 128 + tx * 8);
            const float4  bh  = *(const float4*) (Bs + kk * 128 + tx * 8 + 4);
            ull ap[4] = { __double_as_longlong(a01.x), __double_as_longlong(a01.y),
                          __double_as_longlong(a23.x), __double_as_longlong(a23.y) };
            ull bd[8] = { dup2(bl.x), dup2(bl.y), dup2(bl.z), dup2(bl.w),
                          dup2(bh.x), dup2(bh.y), dup2(bh.z), dup2(bh.w) };
#pragma unroll
            for (int p = 0; p < 4; p++)
#pragma unroll
                for (int j = 0; j < 8; j++) ffma2(acc[p][j], ap[p], bd[j]);
        }
        __syncthreads();
        if (kt + 1 < F_IN / 32) {
            l1_storeA(As, tid, pa);
            l1_storeB(Bs, tid, pb);
            __syncthreads();
        }
    }

    // epilogue 1: bias + relu, transpose-store h0 tile into Hs[m][em]
    float bb[8];
    {
        float4 b1l = ((const float4*)b1)[tx * 2];
        float4 b1h = ((const float4*)b1)[tx * 2 + 1];
        bb[0] = b1l.x; bb[1] = b1l.y; bb[2] = b1l.z; bb[3] = b1l.w;
        bb[4] = b1h.x; bb[5] = b1h.y; bb[6] = b1h.z; bb[7] = b1h.w;
    }
#pragma unroll
    for (int p = 0; p < 4; p++) {
        float r0[8], r1[8];
#pragma unroll
        for (int j = 0; j < 8; j++) {
            float2 v = unpack2(acc[p][j]);
            r0[j] = fmaxf(v.x + bb[j], 0.f);
            r1[j] = fmaxf(v.y + bb[j], 0.f);
        }
        int m0 = ty * 8 + 2 * p;
        *(float4*)(Hs + m0 * LIN1_HSS + tx * 8)           = make_float4(r0[0], r0[1], r0[2], r0[3]);
        *(float4*)(Hs + m0 * LIN1_HSS + tx * 8 + 4)       = make_float4(r0[4], r0[5], r0[6], r0[7]);
        *(float4*)(Hs + (m0 + 1) * LIN1_HSS + tx * 8)     = make_float4(r1[0], r1[1], r1[2], r1[3]);
        *(float4*)(Hs + (m0 + 1) * LIN1_HSS + tx * 8 + 4) = make_float4(r1[4], r1[5], r1[6], r1[7]);
    }
    __syncthreads();

    // epilogue 2: G[128x64] = Hs[128x128] @ Wc1[128x64]
    const int rg = ty, cg = tx;
    ull o[8][2];
#pragma unroll
    for (int i = 0; i < 8; i++) { o[i][0] = 0ull; o[i][1] = 0ull; }

#pragma unroll 4
    for (int em4 = 0; em4 < D_EMB; em4 += 4) {
        double2 bp0 = *(const double2*)(WcS + (em4 + 0) * D_HID + cg * 4);
        double2 bp1 = *(const double2*)(WcS + (em4 + 1) * D_HID + cg * 4);
        double2 bp2 = *(const double2*)(WcS + (em4 + 2) * D_HID + cg * 4);
        double2 bp3 = *(const double2*)(WcS + (em4 + 3) * D_HID + cg * 4);
#pragma unroll
        for (int i = 0; i < 8; i++) {
            float4 a4 = *(const float4*)(Hs + (rg * 8 + i) * LIN1_HSS + em4);
            ull a;
            a = dup2(a4.x);
            ffma2(o[i][0], a, __double_as_longlong(bp0.x));
            ffma2(o[i][1], a, __double_as_longlong(bp0.y));
            a = dup2(a4.y);
            ffma2(o[i][0], a, __double_as_longlong(bp1.x));
            ffma2(o[i][1], a, __double_as_longlong(bp1.y));
            a = dup2(a4.z);
            ffma2(o[i][0], a, __double_as_longlong(bp2.x));
            ffma2(o[i][1], a, __double_as_longlong(bp2.y));
            a = dup2(a4.w);
            ffma2(o[i][0], a, __double_as_longlong(bp3.x));
            ffma2(o[i][1], a, __double_as_longlong(bp3.y));
        }
    }
#pragma unroll
    for (int i = 0; i < 8; i++) {
        int m = rg * 8 + i;
        if (row0 + m < n) {
            float2 lo = unpack2(o[i][0]);
            float2 hi = unpack2(o[i][1]);
            *(float4*)(g1 + (size_t)(row0 + m) * D_HID + cg * 4) =
                make_float4(lo.x, lo.y, hi.x, hi.y);
        }
    }
}

// =====================================================================
// CSR build
// =====================================================================
__global__ void k_zero_int(int* p, int n) {
    int i = blockIdx.x * blockDim.x + threadIdx.x;
    if (i < n) p[i] = 0;
}
__global__ void k_hist(const int* __restrict__ dst, int E, int* __restrict__ deg) {
    int e = blockIdx.x * blockDim.x + threadIdx.x;
    if (e < E) atomicAdd(&deg[dst[e]], 1);
}
__global__ void k_scan1(const int* __restrict__ in, int n,
                        int* __restrict__ incl, int* __restrict__ bsum) {
    __shared__ int s[512];
    int i = blockIdx.x * 512 + threadIdx.x;
    s[threadIdx.x] = (i < n) ? in[i] : 0;
    __syncthreads();
#pragma unroll
    for (int off = 1; off < 512; off <<= 1) {
        int t = (threadIdx.x >= off) ? s[threadIdx.x - off] : 0;
        __syncthreads();
        s[threadIdx.x] += t;
        __syncthreads();
    }
    if (i < n) incl[i] = s[threadIdx.x];
    if (bsum && threadIdx.x == 511) bsum[blockIdx.x] = s[511];
}
__global__ void k_scan3(const int* __restrict__ incl, const int* __restrict__ bsum,
                        const int* __restrict__ deg, int* __restrict__ rp,
                        int* __restrict__ cur, int n) {
    int i = blockIdx.x * blockDim.x + threadIdx.x;
    if (i >= n) return;
    int b = i >> 9;
    int off = (b > 0) ? bsum[b - 1] : 0;
    int v = incl[i] + off;
    rp[i + 1] = v;
    cur[i] = v - deg[i];
    if (i == 0) rp[0] = 0;
}
__global__ void k_fill(const int* __restrict__ src, const int* __restrict__ dst,
                       int E, int* __restrict__ cur, int* __restrict__ col) {
    int e = blockIdx.x * blockDim.x + threadIdx.x;
    if (e >= E) return;
    int pos = atomicAdd(&cur[dst[e]], 1);
    col[pos] = src[e];
}

// =====================================================================
// Canonicalize CSR: sort each node's neighbor segment ascending so the
// aggregation order (and thus fp32 rounding) is identical on every call.
// Warp per node. deg<=32: register bitonic; deg<=1024: smem odd-even;
// beyond: single-lane insertion sort in global (never expected).
// =====================================================================
__global__ void __launch_bounds__(256) k_sortseg(
    const int* __restrict__ rp, int* __restrict__ col, int n)
{
    __shared__ int sbuf[8][1024];
    int lane = threadIdx.x & 31, w = threadIdx.x >> 5;
    int node = blockIdx.x * 8 + w;
    if (node >= n) return;
    int beg = rp[node], end = rp[node + 1];
    int d = end - beg;
    if (d <= 1) return;

    if (d <= 32) {
        int v = (lane < d) ? col[beg + lane] : 0x7fffffff;
#pragma unroll
        for (int k = 2; k <= 32; k <<= 1) {
#pragma unroll
            for (int j = k >> 1; j > 0; j >>= 1) {
                int other = __shfl_xor_sync(0xffffffffu, v, j);
                bool dirUp = ((lane & k) == 0);
                bool takeMin = (((lane & j) == 0) == dirUp);
                v = takeMin ? min(v, other) : max(v, other);
            }
        }
        if (lane < d) col[beg + lane] = v;
    } else if (d <= 1024) {
        int* s = sbuf[w];
        for (int i = lane; i < d; i += 32) s[i] = col[beg + i];
        __syncwarp();
        for (int ph = 0; ph < d; ph++) {
            int start = ph & 1;
            for (int i = start + 2 * lane; i + 1 < d; i += 64) {
                int a = s[i], b = s[i + 1];
                if (a > b) { s[i] = b; s[i + 1] = a; }
            }
            __syncwarp();
        }
        for (int i = lane; i < d; i += 32) col[beg + i] = s[i];
    } else {
        if (lane == 0) {
            for (int i = beg + 1; i < end; i++) {
                int key = col[i];
                int j = i - 1;
                while (j >= beg && col[j] > key) { col[j + 1] = col[j]; j--; }
                col[j + 1] = key;
            }
        }
    }
}

// =====================================================================
// Aggregation: warp per node.  h = relu(mean_nbr(gin) + bias);
// k_agg_mm additionally computes gout = h @ W (64x64 from smem).
// =====================================================================
__device__ __forceinline__ void warp_agg(const float2* __restrict__ gin,
                                         const int* __restrict__ col,
                                         int beg, int end, int lane,
                                         float& ax, float& ay) {
    ax = 0.f; ay = 0.f;
    for (int e0 = beg; e0 < end; e0 += 32) {
        int idx = e0 + lane;
        int c = (idx < end) ? __ldg(&col[idx]) : 0;
        int cnt = min(32, end - e0);
        int j = 0;
        for (; j + 4 <= cnt; j += 4) {
            int s0 = __shfl_sync(0xffffffffu, c, j);
            int s1 = __shfl_sync(0xffffffffu, c, j + 1);
            int s2 = __shfl_sync(0xffffffffu, c, j + 2);
            int s3 = __shfl_sync(0xffffffffu, c, j + 3);
            float2 v0 = gin[s0 * 32 + lane];
            float2 v1 = gin[s1 * 32 + lane];
            float2 v2 = gin[s2 * 32 + lane];
            float2 v3 = gin[s3 * 32 + lane];
            ax += v0.x; ay += v0.y;
            ax += v1.x; ay += v1.y;
            ax += v2.x; ay += v2.y;
            ax += v3.x; ay += v3.y;
        }
        for (; j < cnt; j++) {
            int s = __shfl_sync(0xffffffffu, c, j);
            float2 v = gin[s * 32 + lane];
            ax += v.x; ay += v.y;
        }
    }
}

__global__ void __launch_bounds__(256) k_agg_mm(
    const float2* __restrict__ gin, float2* __restrict__ gout,
    const int* __restrict__ rp, const int* __restrict__ col,
    const float* __restrict__ bias, const float* __restrict__ W, int n)
{
    __shared__ float Ws[D_HID * D_HID];
    __shared__ float hbuf[8][D_HID];
    int tid = threadIdx.x;
    {
        const float4* s = (const float4*)W;
        float4* d = (float4*)Ws;
#pragma unroll
        for (int i = 0; i < 4; i++) d[tid + i * 256] = s[tid + i * 256];
    }
    __syncthreads();
    int lane = tid & 31, w = tid >> 5;
    int node = blockIdx.x * 8 + w;
    if (node >= n) return;
    int beg = rp[node], end = rp[node + 1];
    float ax, ay;
    warp_agg(gin, col, beg, end, lane, ax, ay);
    float inv = 1.f / fmaxf((float)(end - beg), 1.f);
    float b0 = bias[2 * lane], b1v = bias[2 * lane + 1];
    hbuf[w][2 * lane]     = fmaxf(fmaf(ax, inv, b0), 0.f);
    hbuf[w][2 * lane + 1] = fmaxf(fmaf(ay, inv, b1v), 0.f);
    __syncwarp();
    float2 o = make_float2(0.f, 0.f);
#pragma unroll
    for (int k = 0; k < D_HID; k++) {
        float hv = hbuf[w][k];
        float2 wv = ((const float2*)Ws)[k * 32 + lane];
        o.x = fmaf(hv, wv.x, o.x);
        o.y = fmaf(hv, wv.y, o.y);
    }
    gout[node * 32 + lane] = o;
}

__global__ void __launch_bounds__(256) k_agg_final(
    const float2* __restrict__ gin, float2* __restrict__ gout,
    const int* __restrict__ rp, const int* __restrict__ col,
    const float* __restrict__ bias, int n)
{
    int tid = threadIdx.x;
    int lane = tid & 31, w = tid >> 5;
    int node = blockIdx.x * 8 + w;
    if (node >= n) return;
    int beg = rp[node], end = rp[node + 1];
    float ax, ay;
    warp_agg(gin, col, beg, end, lane, ax, ay);
    float inv = 1.f / fmaxf((float)(end - beg), 1.f);
    float b0 = bias[2 * lane], b1v = bias[2 * lane + 1];
    float2 h;
    h.x = fmaxf(fmaf(ax, inv, b0), 0.f);
    h.y = fmaxf(fmaf(ay, inv, b1v), 0.f);
    gout[node * 32 + lane] = h;
}

// =====================================================================
// Deterministic two-pass batchnorm statistics
// pass 1: per-block partial sums -> g_part (fixed slots), ordered reduce -> mean
// pass 2: per-block partial sum of (x-mean)^2 -> ordered reduce -> scale/offset
// =====================================================================
__global__ void __launch_bounds__(256) k_sum_mean(
    const float* __restrict__ h, int n, float* __restrict__ part)
{
    __shared__ float sb[4][64];
    int f = threadIdx.x & 63;
    int ty = threadIdx.x >> 6;
    float s = 0.f;
    for (int r = blockIdx.x * 4 + ty; r < n; r += gridDim.x * 4)
        s += h[(size_t)r * 64 + f];
    sb[ty][f] = s;
    __syncthreads();
    if (threadIdx.x < 64) {
        float t = ((sb[0][f] + sb[1][f]) + sb[2][f]) + sb[3][f];
        part[blockIdx.x * 64 + f] = t;
    }
}
__global__ void k_reduce_mean(const float* __restrict__ part, int nb, int n,
                              float* __restrict__ stats)
{
    int f = threadIdx.x;   // 64 threads
    float s = 0.f;
    for (int b = 0; b < nb; b++) s += part[b * 64 + f];
    stats[f] = s / (float)n;
}
__global__ void __launch_bounds__(256) k_sum_var(
    const float* __restrict__ h, int n, const float* __restrict__ stats,
    float* __restrict__ part)
{
    __shared__ float sb[4][64];
    int f = threadIdx.x & 63;
    int ty = threadIdx.x >> 6;
    float mean = stats[f];
    float s = 0.f;
    for (int r = blockIdx.x * 4 + ty; r < n; r += gridDim.x * 4) {
        float d = h[(size_t)r * 64 + f] - mean;
        s = fmaf(d, d, s);
    }
    sb[ty][f] = s;
    __syncthreads();
    if (threadIdx.x < 64) {
        float t = ((sb[0][f] + sb[1][f]) + sb[2][f]) + sb[3][f];
        part[blockIdx.x * 64 + f] = t;
    }
}
__global__ void k_reduce_var(const float* __restrict__ part, int nb, int n,
                             const float* __restrict__ gamma,
                             const float* __restrict__ beta,
                             float* __restrict__ stats)
{
    int f = threadIdx.x;   // 64 threads
    float s = 0.f;
    for (int b = 0; b < nb; b++) s += part[b * 64 + f];
    float var = s / (float)n;
    float mean = stats[f];
    float rstd = rsqrtf(var + 1e-5f);
    float sc = rstd * gamma[f];
    stats[128 + f] = sc;
    stats[192 + f] = beta[f] - mean * sc;
}

// =====================================================================
// Final head: batchnorm-apply -> lin2 relu -> lin3
// =====================================================================
__global__ void __launch_bounds__(256) k_final(
    const float2* __restrict__ h3, const float* __restrict__ stats,
    const float* __restrict__ W2, const float* __restrict__ b2,
    const float* __restrict__ W3, const float* __restrict__ b3,
    float* __restrict__ out, int n)
{
    __shared__ float W2s[D_HID * N_CLS];   // 2048
    __shared__ float W3s[N_CLS * N_CLS];   // 1024
    __shared__ float hb[8][D_HID];
    __shared__ float tb[8][N_CLS];
    int tid = threadIdx.x;
    {
        const float4* s2 = (const float4*)W2;
        float4* d2 = (float4*)W2s;
        d2[tid] = s2[tid];
        d2[tid + 256] = s2[tid + 256];
        ((float4*)W3s)[tid] = ((const float4*)W3)[tid];
    }
    __syncthreads();
    int lane = tid & 31, w = tid >> 5;
    int node = blockIdx.x * 8 + w;
    if (node >= n) return;
    float2 h = h3[node * 32 + lane];
    float s0 = stats[128 + 2 * lane], s1 = stats[128 + 2 * lane + 1];
    float t0 = stats[192 + 2 * lane], t1 = stats[192 + 2 * lane + 1];
    hb[w][2 * lane]     = fmaf(h.x, s0, t0);
    hb[w][2 * lane + 1] = fmaf(h.y, s1, t1);
    __syncwarp();
    float t = b2[lane];
#pragma unroll
    for (int k = 0; k < D_HID; k++) t = fmaf(hb[w][k], W2s[k * 32 + lane], t);
    t = fmaxf(t, 0.f);
    tb[w][lane] = t;
    __syncwarp();
    float o = b3[lane];
#pragma unroll
    for (int k = 0; k < N_CLS; k++) o = fmaf(tb[w][k], W3s[k * 32 + lane], o);
    out[(size_t)node * 32 + lane] = o;
}

// =====================================================================
// launch
// =====================================================================
extern "C" void kernel_launch(void* const* d_in, const int* in_sizes, int n_in,
                              void* d_out, int out_size) {
    const float* x     = (const float*)d_in[0];
    const float* W1    = (const float*)d_in[1];
    const float* b1    = (const float*)d_in[2];
    const float* Wc1   = (const float*)d_in[3];
    const float* bc1   = (const float*)d_in[4];
    const float* Wc2   = (const float*)d_in[5];
    const float* bc2   = (const float*)d_in[6];
    const float* Wc3   = (const float*)d_in[7];
    const float* bc3   = (const float*)d_in[8];
    const float* gamma = (const float*)d_in[9];
    const float* beta  = (const float*)d_in[10];
    const float* W2    = (const float*)d_in[11];
    const float* b2    = (const float*)d_in[12];
    const float* W3    = (const float*)d_in[13];
    const float* b3    = (const float*)d_in[14];
    const int*   ei    = (const int*)d_in[15];

    int n = in_sizes[0] / F_IN;
    int E = in_sizes[15] / 2;
    const int* src = ei;
    const int* dst = ei + E;

    float *bufA, *bufB, *stats, *part;
    int *deg, *incl, *bsum, *rp, *cur, *colb;
    cudaGetSymbolAddress((void**)&bufA, g_bufA);
    cudaGetSymbolAddress((void**)&bufB, g_bufB);
    cudaGetSymbolAddress((void**)&stats, g_stats);
    cudaGetSymbolAddress((void**)&part, g_part);
    cudaGetSymbolAddress((void**)&deg, g_deg);
    cudaGetSymbolAddress((void**)&incl, g_incl);
    cudaGetSymbolAddress((void**)&bsum, g_bsum);
    cudaGetSymbolAddress((void**)&rp, g_rp);
    cudaGetSymbolAddress((void**)&cur, g_cur);
    cudaGetSymbolAddress((void**)&colb, g_col);

    cudaFuncSetAttribute(k_lin1, cudaFuncAttributeMaxDynamicSharedMemorySize, LIN1_SMEM);

    // fused lin1 + Wc1
    k_lin1<<<(n + 127) / 128, 256, LIN1_SMEM>>>(x, W1, b1, Wc1, bufA, n);

    // CSR build (+ canonical per-node order for determinism)
    k_zero_int<<<(n + 255) / 256, 256>>>(deg, n);
    k_hist<<<(E + 255) / 256, 256>>>(dst, E, deg);
    int NB = (n + 511) / 512;
    k_scan1<<<NB, 512>>>(deg, n, incl, bsum);
    k_scan1<<<1, 512>>>(bsum, NB, bsum, (int*)0);
    k_scan3<<<(n + 255) / 256, 256>>>(incl, bsum, deg, rp, cur, n);
    k_fill<<<(E + 255) / 256, 256>>>(src, dst, E, cur, colb);
    int ablocks = (n + 7) / 8;
    k_sortseg<<<ablocks, 256>>>(rp, colb, n);

    // conv1 (+Wc2 pre-applied), conv2 (+Wc3 pre-applied), conv3
    k_agg_mm<<<ablocks, 256>>>((const float2*)bufA, (float2*)bufB, rp, colb, bc1, Wc2, n);
    k_agg_mm<<<ablocks, 256>>>((const float2*)bufB, (float2*)bufA, rp, colb, bc2, Wc3, n);
    k_agg_final<<<ablocks, 256>>>((const float2*)bufA, (float2*)bufB, rp, colb, bc3, n);

    // deterministic two-pass batchnorm stats + head
    k_sum_mean<<<256, 256>>>(bufB, n, part);
    k_reduce_mean<<<1, 64>>>(part, 256, n, stats);
    k_sum_var<<<256, 256>>>(bufB, n, stats, part);
    k_reduce_var<<<1, 64>>>(part, 256, n, gamma, beta, stats);
    k_final<<<ablocks, 256>>>((const float2*)bufB, stats, W2, b2, W3, b3,
                              (float*)d_out, n);
}

// round 3
// speedup vs baseline: 1.0398x; 1.0398x over previous
#include <cuda_runtime.h>
#include <cuda_bf16.h>

typedef unsigned long long ull;

#define F_IN   512
#define D_EMB  128
#define D_HID  64
#define N_CLS  32
#define MAXN   100000
#define MAXE   1600000

// ---------------- device scratch (no allocation allowed) ----------------
__device__ float g_bufA[MAXN * D_HID];
__device__ float g_bufB[MAXN * D_HID];
__device__ int   g_deg [MAXN + 2];
__device__ int   g_incl[MAXN + 2];
__device__ int   g_bsum[512];
__device__ int   g_rp  [MAXN + 2];
__device__ int   g_cur [MAXN + 2];
__device__ int   g_col [MAXE + 2];
__device__ float g_stats[256];
__device__ float g_part[256 * 64];

// ---------------- f32x2 packed-FMA helpers ----------------
__device__ __forceinline__ ull dup2(float v) {
    ull r; asm("mov.b64 %0, {%1, %1};" : "=l"(r) : "f"(v)); return r;
}
__device__ __forceinline__ void ffma2(ull &acc, ull a, ull b) {
    asm("fma.rn.f32x2 %0, %1, %2, %0;" : "+l"(acc) : "l"(a), "l"(b));
}
__device__ __forceinline__ float2 unpack2(ull v) {
    float2 r; asm("mov.b64 {%0, %1}, %2;" : "=f"(r.x), "=f"(r.y) : "l"(v)); return r;
}

// =====================================================================
// K1: g1 = relu(x @ W1 + b1) @ Wc1      [n x 64]
// =====================================================================
#define LIN1_HSS 132
#define LIN1_SMEM ((D_EMB*D_HID + 128*LIN1_HSS) * 4)

__device__ __forceinline__ void l1_fetchA(const float* __restrict__ x, int n,
                                          int row0, int k0, int tid, float4* pa) {
    int m = tid & 127, cc = tid >> 7;
    const float4* p = (const float4*)(x + (size_t)(row0 + m) * F_IN + k0 + cc * 16);
    bool v = (row0 + m) < n;
#pragma unroll
    for (int i = 0; i < 4; i++)
        pa[i] = v ? p[i] : make_float4(0.f, 0.f, 0.f, 0.f);
}
__device__ __forceinline__ void l1_storeA(float* As, int tid, const float4* pa) {
    int m = tid & 127, cc = tid >> 7;
#pragma unroll
    for (int i = 0; i < 4; i++) {
        int kk = cc * 16 + i * 4;
        As[(kk + 0) * 128 + m] = pa[i].x;
        As[(kk + 1) * 128 + m] = pa[i].y;
        As[(kk + 2) * 128 + m] = pa[i].z;
        As[(kk + 3) * 128 + m] = pa[i].w;
    }
}
__device__ __forceinline__ void l1_fetchB(const float* __restrict__ W1,
                                          int k0, int tid, float4* pb) {
    const float4* p = (const float4*)(W1 + (size_t)k0 * D_EMB);
#pragma unroll
    for (int i = 0; i < 4; i++) pb[i] = p[tid + i * 256];
}
__device__ __forceinline__ void l1_storeB(float* Bs, int tid, const float4* pb) {
#pragma unroll
    for (int i = 0; i < 4; i++) ((float4*)Bs)[tid + i * 256] = pb[i];
}

__global__ void __launch_bounds__(256) k_lin1(
    const float* __restrict__ x, const float* __restrict__ W1,
    const float* __restrict__ b1, const float* __restrict__ Wc1,
    float* __restrict__ g1, int n)
{
    extern __shared__ float smem[];
    float* WcS = smem;
    float* As  = smem + D_EMB * D_HID;
    float* Bs  = As + 32 * 128;
    float* Hs  = smem + D_EMB * D_HID;

    const int tid = threadIdx.x;
    const int tx = tid & 15, ty = tid >> 4;
    const int row0 = blockIdx.x * 128;

    {
        const float4* s = (const float4*)Wc1;
        float4* d = (float4*)WcS;
#pragma unroll
        for (int i = 0; i < 8; i++) d[tid + i * 256] = s[tid + i * 256];
    }

    ull acc[4][8];
#pragma unroll
    for (int p = 0; p < 4; p++)
#pragma unroll
        for (int j = 0; j < 8; j++) acc[p][j] = 0ull;

    float4 pa[4], pb[4];
    l1_fetchA(x, n, row0, 0, tid, pa);
    l1_fetchB(W1, 0, tid, pb);
    l1_storeA(As, tid, pa);
    l1_storeB(Bs, tid, pb);
    __syncthreads();

    for (int kt = 0; kt < F_IN / 32; kt++) {
        if (kt + 1 < F_IN / 32) {
            l1_fetchA(x, n, row0, (kt + 1) * 32, tid, pa);
            l1_fetchB(W1, (kt + 1) * 32, tid, pb);
        }
#pragma unroll 8
        for (int kk = 0; kk < 32; kk++) {
            const double2 a01 = *(const double2*)(As + kk * 128 + ty * 8);
            const double2 a23 = *(const double2*)(As + kk * 128 + ty * 8 + 4);
            const float4  bl  = *(const float4*) (Bs + kk * 128 + tx * 8);
            const float4  bh  = *(const float4*) (Bs + kk * 128 + tx * 8 + 4);
            ull ap[4] = { __double_as_longlong(a01.x), __double_as_longlong(a01.y),
                          __double_as_longlong(a23.x), __double_as_longlong(a23.y) };
            ull bd[8] = { dup2(bl.x), dup2(bl.y), dup2(bl.z), dup2(bl.w),
                          dup2(bh.x), dup2(bh.y), dup2(bh.z), dup2(bh.w) };
#pragma unroll
            for (int p = 0; p < 4; p++)
#pragma unroll
                for (int j = 0; j < 8; j++) ffma2(acc[p][j], ap[p], bd[j]);
        }
        __syncthreads();
        if (kt + 1 < F_IN / 32) {
            l1_storeA(As, tid, pa);
            l1_storeB(Bs, tid, pb);
            __syncthreads();
        }
    }

    float bb[8];
    {
        float4 b1l = ((const float4*)b1)[tx * 2];
        float4 b1h = ((const float4*)b1)[tx * 2 + 1];
        bb[0] = b1l.x; bb[1] = b1l.y; bb[2] = b1l.z; bb[3] = b1l.w;
        bb[4] = b1h.x; bb[5] = b1h.y; bb[6] = b1h.z; bb[7] = b1h.w;
    }
#pragma unroll
    for (int p = 0; p < 4; p++) {
        float r0[8], r1[8];
#pragma unroll
        for (int j = 0; j < 8; j++) {
            float2 v = unpack2(acc[p][j]);
            r0[j] = fmaxf(v.x + bb[j], 0.f);
            r1[j] = fmaxf(v.y + bb[j], 0.f);
        }
        int m0 = ty * 8 + 2 * p;
        *(float4*)(Hs + m0 * LIN1_HSS + tx * 8)           = make_float4(r0[0], r0[1], r0[2], r0[3]);
        *(float4*)(Hs + m0 * LIN1_HSS + tx * 8 + 4)       = make_float4(r0[4], r0[5], r0[6], r0[7]);
        *(float4*)(Hs + (m0 + 1) * LIN1_HSS + tx * 8)     = make_float4(r1[0], r1[1], r1[2], r1[3]);
        *(float4*)(Hs + (m0 + 1) * LIN1_HSS + tx * 8 + 4) = make_float4(r1[4], r1[5], r1[6], r1[7]);
    }
    __syncthreads();

    const int rg = ty, cg = tx;
    ull o[8][2];
#pragma unroll
    for (int i = 0; i < 8; i++) { o[i][0] = 0ull; o[i][1] = 0ull; }

#pragma unroll 4
    for (int em4 = 0; em4 < D_EMB; em4 += 4) {
        double2 bp0 = *(const double2*)(WcS + (em4 + 0) * D_HID + cg * 4);
        double2 bp1 = *(const double2*)(WcS + (em4 + 1) * D_HID + cg * 4);
        double2 bp2 = *(const double2*)(WcS + (em4 + 2) * D_HID + cg * 4);
        double2 bp3 = *(const double2*)(WcS + (em4 + 3) * D_HID + cg * 4);
#pragma unroll
        for (int i = 0; i < 8; i++) {
            float4 a4 = *(const float4*)(Hs + (rg * 8 + i) * LIN1_HSS + em4);
            ull a;
            a = dup2(a4.x);
            ffma2(o[i][0], a, __double_as_longlong(bp0.x));
            ffma2(o[i][1], a, __double_as_longlong(bp0.y));
            a = dup2(a4.y);
            ffma2(o[i][0], a, __double_as_longlong(bp1.x));
            ffma2(o[i][1], a, __double_as_longlong(bp1.y));
            a = dup2(a4.z);
            ffma2(o[i][0], a, __double_as_longlong(bp2.x));
            ffma2(o[i][1], a, __double_as_longlong(bp2.y));
            a = dup2(a4.w);
            ffma2(o[i][0], a, __double_as_longlong(bp3.x));
            ffma2(o[i][1], a, __double_as_longlong(bp3.y));
        }
    }
#pragma unroll
    for (int i = 0; i < 8; i++) {
        int m = rg * 8 + i;
        if (row0 + m < n) {
            float2 lo = unpack2(o[i][0]);
            float2 hi = unpack2(o[i][1]);
            *(float4*)(g1 + (size_t)(row0 + m) * D_HID + cg * 4) =
                make_float4(lo.x, lo.y, hi.x, hi.y);
        }
    }
}

// =====================================================================
// CSR build
// =====================================================================
__global__ void k_zero_int(int* p, int n) {
    int i = blockIdx.x * blockDim.x + threadIdx.x;
    if (i < n) p[i] = 0;
}
__global__ void k_hist(const int* __restrict__ dst, int E, int* __restrict__ deg) {
    int e = blockIdx.x * blockDim.x + threadIdx.x;
    if (e < E) atomicAdd(&deg[dst[e]], 1);
}
__global__ void k_scan1(const int* __restrict__ in, int n,
                        int* __restrict__ incl, int* __restrict__ bsum) {
    __shared__ int s[512];
    int i = blockIdx.x * 512 + threadIdx.x;
    s[threadIdx.x] = (i < n) ? in[i] : 0;
    __syncthreads();
#pragma unroll
    for (int off = 1; off < 512; off <<= 1) {
        int t = (threadIdx.x >= off) ? s[threadIdx.x - off] : 0;
        __syncthreads();
        s[threadIdx.x] += t;
        __syncthreads();
    }
    if (i < n) incl[i] = s[threadIdx.x];
    if (bsum && threadIdx.x == 511) bsum[blockIdx.x] = s[511];
}
__global__ void k_scan3(const int* __restrict__ incl, const int* __restrict__ bsum,
                        const int* __restrict__ deg, int* __restrict__ rp,
                        int* __restrict__ cur, int n) {
    int i = blockIdx.x * blockDim.x + threadIdx.x;
    if (i >= n) return;
    int b = i >> 9;
    int off = (b > 0) ? bsum[b - 1] : 0;
    int v = incl[i] + off;
    rp[i + 1] = v;
    cur[i] = v - deg[i];
    if (i == 0) rp[0] = 0;
}
__global__ void k_fill(const int* __restrict__ src, const int* __restrict__ dst,
                       int E, int* __restrict__ cur, int* __restrict__ col) {
    int e = blockIdx.x * blockDim.x + threadIdx.x;
    if (e >= E) return;
    int pos = atomicAdd(&cur[dst[e]], 1);
    col[pos] = src[e];
}

// =====================================================================
// Canonicalize CSR segment order (determinism)
// =====================================================================
__global__ void __launch_bounds__(256) k_sortseg(
    const int* __restrict__ rp, int* __restrict__ col, int n)
{
    __shared__ int sbuf[8][1024];
    int lane = threadIdx.x & 31, w = threadIdx.x >> 5;
    int node = blockIdx.x * 8 + w;
    if (node >= n) return;
    int beg = rp[node], end = rp[node + 1];
    int d = end - beg;
    if (d <= 1) return;

    if (d <= 32) {
        int v = (lane < d) ? col[beg + lane] : 0x7fffffff;
#pragma unroll
        for (int k = 2; k <= 32; k <<= 1) {
#pragma unroll
            for (int j = k >> 1; j > 0; j >>= 1) {
                int other = __shfl_xor_sync(0xffffffffu, v, j);
                bool dirUp = ((lane & k) == 0);
                bool takeMin = (((lane & j) == 0) == dirUp);
                v = takeMin ? min(v, other) : max(v, other);
            }
        }
        if (lane < d) col[beg + lane] = v;
    } else if (d <= 1024) {
        int* s = sbuf[w];
        for (int i = lane; i < d; i += 32) s[i] = col[beg + i];
        __syncwarp();
        for (int ph = 0; ph < d; ph++) {
            int start = ph & 1;
            for (int i = start + 2 * lane; i + 1 < d; i += 64) {
                int a = s[i], b = s[i + 1];
                if (a > b) { s[i] = b; s[i + 1] = a; }
            }
            __syncwarp();
        }
        for (int i = lane; i < d; i += 32) col[beg + i] = s[i];
    } else {
        if (lane == 0) {
            for (int i = beg + 1; i < end; i++) {
                int key = col[i];
                int j = i - 1;
                while (j >= beg && col[j] > key) { col[j + 1] = col[j]; j--; }
                col[j + 1] = key;
            }
        }
    }
}

// =====================================================================
// Aggregation: warp per node, MLP=8 gather.
// =====================================================================
__device__ __forceinline__ void warp_agg(const float2* __restrict__ gin,
                                         const int* __restrict__ col,
                                         int beg, int end, int lane,
                                         float& ax, float& ay) {
    ax = 0.f; ay = 0.f;
    for (int e0 = beg; e0 < end; e0 += 32) {
        int idx = e0 + lane;
        int c = (idx < end) ? __ldg(&col[idx]) : 0;
        int cnt = min(32, end - e0);
        int j = 0;
        for (; j + 8 <= cnt; j += 8) {
            int s0 = __shfl_sync(0xffffffffu, c, j);
            int s1 = __shfl_sync(0xffffffffu, c, j + 1);
            int s2 = __shfl_sync(0xffffffffu, c, j + 2);
            int s3 = __shfl_sync(0xffffffffu, c, j + 3);
            int s4 = __shfl_sync(0xffffffffu, c, j + 4);
            int s5 = __shfl_sync(0xffffffffu, c, j + 5);
            int s6 = __shfl_sync(0xffffffffu, c, j + 6);
            int s7 = __shfl_sync(0xffffffffu, c, j + 7);
            float2 v0 = gin[s0 * 32 + lane];
            float2 v1 = gin[s1 * 32 + lane];
            float2 v2 = gin[s2 * 32 + lane];
            float2 v3 = gin[s3 * 32 + lane];
            float2 v4 = gin[s4 * 32 + lane];
            float2 v5 = gin[s5 * 32 + lane];
            float2 v6 = gin[s6 * 32 + lane];
            float2 v7 = gin[s7 * 32 + lane];
            ax += v0.x; ay += v0.y;
            ax += v1.x; ay += v1.y;
            ax += v2.x; ay += v2.y;
            ax += v3.x; ay += v3.y;
            ax += v4.x; ay += v4.y;
            ax += v5.x; ay += v5.y;
            ax += v6.x; ay += v6.y;
            ax += v7.x; ay += v7.y;
        }
        for (; j < cnt; j++) {
            int s = __shfl_sync(0xffffffffu, c, j);
            float2 v = gin[s * 32 + lane];
            ax += v.x; ay += v.y;
        }
    }
}

// agg + fused 64x64 MM.  Gather: warp per node (8 nodes/block).
// MM: warps 0-3, each computes 2 nodes that SHARE the Ws row loads,
// accumulators packed across the node pair (f32x2).
#define HT_STRIDE 10
__global__ void __launch_bounds__(256) k_agg_mm(
    const float2* __restrict__ gin, float2* __restrict__ gout,
    const int* __restrict__ rp, const int* __restrict__ col,
    const float* __restrict__ bias, const float* __restrict__ W, int n)
{
    __shared__ float Ws[D_HID * D_HID];
    __shared__ float hT[D_HID][HT_STRIDE];   // hT[k][node-in-block]
    int tid = threadIdx.x;
    {
        const float4* s = (const float4*)W;
        float4* d = (float4*)Ws;
#pragma unroll
        for (int i = 0; i < 4; i++) d[tid + i * 256] = s[tid + i * 256];
    }
    int lane = tid & 31, w = tid >> 5;
    int node = blockIdx.x * 8 + w;
    if (node < n) {
        int beg = rp[node], end = rp[node + 1];
        float ax, ay;
        warp_agg(gin, col, beg, end, lane, ax, ay);
        float inv = 1.f / fmaxf((float)(end - beg), 1.f);
        float b0 = bias[2 * lane], b1v = bias[2 * lane + 1];
        hT[2 * lane][w]     = fmaxf(fmaf(ax, inv, b0), 0.f);
        hT[2 * lane + 1][w] = fmaxf(fmaf(ay, inv, b1v), 0.f);
    }
    __syncthreads();
    if (w < 4) {
        int n0 = blockIdx.x * 8 + 2 * w;
        if (n0 < n) {
            int n1 = n0 + 1;
            const float2* wsp = (const float2*)Ws;
            ull oXe = 0ull, oXo = 0ull, oYe = 0ull, oYo = 0ull;
#pragma unroll
            for (int k = 0; k < D_HID; k += 2) {
                ull h0 = *(const ull*)(&hT[k][2 * w]);      // {h_n0[k], h_n1[k]}
                ull h1 = *(const ull*)(&hT[k + 1][2 * w]);
                float2 w0 = wsp[k * 32 + lane];
                float2 w1 = wsp[(k + 1) * 32 + lane];
                ffma2(oXe, h0, dup2(w0.x));
                ffma2(oYe, h0, dup2(w0.y));
                ffma2(oXo, h1, dup2(w1.x));
                ffma2(oYo, h1, dup2(w1.y));
            }
            float2 xe = unpack2(oXe), xo = unpack2(oXo);
            float2 ye = unpack2(oYe), yo = unpack2(oYo);
            gout[n0 * 32 + lane] = make_float2(xe.x + xo.x, ye.x + yo.x);
            if (n1 < n)
                gout[n1 * 32 + lane] = make_float2(xe.y + xo.y, ye.y + yo.y);
        }
    }
}

__global__ void __launch_bounds__(256) k_agg_final(
    const float2* __restrict__ gin, float2* __restrict__ gout,
    const int* __restrict__ rp, const int* __restrict__ col,
    const float* __restrict__ bias, int n)
{
    int tid = threadIdx.x;
    int lane = tid & 31, w = tid >> 5;
    int node = blockIdx.x * 8 + w;
    if (node >= n) return;
    int beg = rp[node], end = rp[node + 1];
    float ax, ay;
    warp_agg(gin, col, beg, end, lane, ax, ay);
    float inv = 1.f / fmaxf((float)(end - beg), 1.f);
    float b0 = bias[2 * lane], b1v = bias[2 * lane + 1];
    float2 h;
    h.x = fmaxf(fmaf(ax, inv, b0), 0.f);
    h.y = fmaxf(fmaf(ay, inv, b1v), 0.f);
    gout[node * 32 + lane] = h;
}

// =====================================================================
// Deterministic two-pass batchnorm statistics
// =====================================================================
__global__ void __launch_bounds__(256) k_sum_mean(
    const float* __restrict__ h, int n, float* __restrict__ part)
{
    __shared__ float sb[4][64];
    int f = threadIdx.x & 63;
    int ty = threadIdx.x >> 6;
    float s = 0.f;
    for (int r = blockIdx.x * 4 + ty; r < n; r += gridDim.x * 4)
        s += h[(size_t)r * 64 + f];
    sb[ty][f] = s;
    __syncthreads();
    if (threadIdx.x < 64) {
        float t = ((sb[0][f] + sb[1][f]) + sb[2][f]) + sb[3][f];
        part[blockIdx.x * 64 + f] = t;
    }
}
__global__ void k_reduce_mean(const float* __restrict__ part, int nb, int n,
                              float* __restrict__ stats)
{
    int f = threadIdx.x;
    float s = 0.f;
    for (int b = 0; b < nb; b++) s += part[b * 64 + f];
    stats[f] = s / (float)n;
}
__global__ void __launch_bounds__(256) k_sum_var(
    const float* __restrict__ h, int n, const float* __restrict__ stats,
    float* __restrict__ part)
{
    __shared__ float sb[4][64];
    int f = threadIdx.x & 63;
    int ty = threadIdx.x >> 6;
    float mean = stats[f];
    float s = 0.f;
    for (int r = blockIdx.x * 4 + ty; r < n; r += gridDim.x * 4) {
        float d = h[(size_t)r * 64 + f] - mean;
        s = fmaf(d, d, s);
    }
    sb[ty][f] = s;
    __syncthreads();
    if (threadIdx.x < 64) {
        float t = ((sb[0][f] + sb[1][f]) + sb[2][f]) + sb[3][f];
        part[blockIdx.x * 64 + f] = t;
    }
}
__global__ void k_reduce_var(const float* __restrict__ part, int nb, int n,
                             const float* __restrict__ gamma,
                             const float* __restrict__ beta,
                             float* __restrict__ stats)
{
    int f = threadIdx.x;
    float s = 0.f;
    for (int b = 0; b < nb; b++) s += part[b * 64 + f];
    float var = s / (float)n;
    float mean = stats[f];
    float rstd = rsqrtf(var + 1e-5f);
    float sc = rstd * gamma[f];
    stats[128 + f] = sc;
    stats[192 + f] = beta[f] - mean * sc;
}

// =====================================================================
// Final head
// =====================================================================
__global__ void __launch_bounds__(256) k_final(
    const float2* __restrict__ h3, const float* __restrict__ stats,
    const float* __restrict__ W2, const float* __restrict__ b2,
    const float* __restrict__ W3, const float* __restrict__ b3,
    float* __restrict__ out, int n)
{
    __shared__ float W2s[D_HID * N_CLS];
    __shared__ float W3s[N_CLS * N_CLS];
    __shared__ float hb[8][D_HID];
    __shared__ float tb[8][N_CLS];
    int tid = threadIdx.x;
    {
        const float4* s2 = (const float4*)W2;
        float4* d2 = (float4*)W2s;
        d2[tid] = s2[tid];
        d2[tid + 256] = s2[tid + 256];
        ((float4*)W3s)[tid] = ((const float4*)W3)[tid];
    }
    __syncthreads();
    int lane = tid & 31, w = tid >> 5;
    int node = blockIdx.x * 8 + w;
    if (node >= n) return;
    float2 h = h3[node * 32 + lane];
    float s0 = stats[128 + 2 * lane], s1 = stats[128 + 2 * lane + 1];
    float t0 = stats[192 + 2 * lane], t1 = stats[192 + 2 * lane + 1];
    hb[w][2 * lane]     = fmaf(h.x, s0, t0);
    hb[w][2 * lane + 1] = fmaf(h.y, s1, t1);
    __syncwarp();
    float t = b2[lane];
#pragma unroll
    for (int k = 0; k < D_HID; k++) t = fmaf(hb[w][k], W2s[k * 32 + lane], t);
    t = fmaxf(t, 0.f);
    tb[w][lane] = t;
    __syncwarp();
    float o = b3[lane];
#pragma unroll
    for (int k = 0; k < N_CLS; k++) o = fmaf(tb[w][k], W3s[k * 32 + lane], o);
    out[(size_t)node * 32 + lane] = o;
}

// =====================================================================
// launch  (order chosen so k_lin1 sits in the ncu-profiled slot #4)
// =====================================================================
extern "C" void kernel_launch(void* const* d_in, const int* in_sizes, int n_in,
                              void* d_out, int out_size) {
    const float* x     = (const float*)d_in[0];
    const float* W1    = (const float*)d_in[1];
    const float* b1    = (const float*)d_in[2];
    const float* Wc1   = (const float*)d_in[3];
    const float* bc1   = (const float*)d_in[4];
    const float* Wc2   = (const float*)d_in[5];
    const float* bc2   = (const float*)d_in[6];
    const float* Wc3   = (const float*)d_in[7];
    const float* bc3   = (const float*)d_in[8];
    const float* gamma = (const float*)d_in[9];
    const float* beta  = (const float*)d_in[10];
    const float* W2    = (const float*)d_in[11];
    const float* b2    = (const float*)d_in[12];
    const float* W3    = (const float*)d_in[13];
    const float* b3    = (const float*)d_in[14];
    const int*   ei    = (const int*)d_in[15];

    int n = in_sizes[0] / F_IN;
    int E = in_sizes[15] / 2;
    const int* src = ei;
    const int* dst = ei + E;

    float *bufA, *bufB, *stats, *part;
    int *deg, *incl, *bsum, *rp, *cur, *colb;
    cudaGetSymbolAddress((void**)&bufA, g_bufA);
    cudaGetSymbolAddress((void**)&bufB, g_bufB);
    cudaGetSymbolAddress((void**)&stats, g_stats);
    cudaGetSymbolAddress((void**)&part, g_part);
    cudaGetSymbolAddress((void**)&deg, g_deg);
    cudaGetSymbolAddress((void**)&incl, g_incl);
    cudaGetSymbolAddress((void**)&bsum, g_bsum);
    cudaGetSymbolAddress((void**)&rp, g_rp);
    cudaGetSymbolAddress((void**)&cur, g_cur);
    cudaGetSymbolAddress((void**)&colb, g_col);

    cudaFuncSetAttribute(k_lin1, cudaFuncAttributeMaxDynamicSharedMemorySize, LIN1_SMEM);

    int NB = (n + 511) / 512;
    int ablocks = (n + 7) / 8;

    // CSR-prefix kernels first; k_lin1 in launch slot #4 (ncu capture slot).
    k_zero_int<<<(n + 255) / 256, 256>>>(deg, n);
    k_hist<<<(E + 255) / 256, 256>>>(dst, E, deg);
    k_scan1<<<NB, 512>>>(deg, n, incl, bsum);
    k_lin1<<<(n + 127) / 128, 256, LIN1_SMEM>>>(x, W1, b1, Wc1, bufA, n);
    k_scan1<<<1, 512>>>(bsum, NB, bsum, (int*)0);
    k_scan3<<<(n + 255) / 256, 256>>>(incl, bsum, deg, rp, cur, n);
    k_fill<<<(E + 255) / 256, 256>>>(src, dst, E, cur, colb);
    k_sortseg<<<ablocks, 256>>>(rp, colb, n);

    // conv1 (+Wc2 pre-applied), conv2 (+Wc3 pre-applied), conv3
    k_agg_mm<<<ablocks, 256>>>((const float2*)bufA, (float2*)bufB, rp, colb, bc1, Wc2, n);
    k_agg_mm<<<ablocks, 256>>>((const float2*)bufB, (float2*)bufA, rp, colb, bc2, Wc3, n);
    k_agg_final<<<ablocks, 256>>>((const float2*)bufA, (float2*)bufB, rp, colb, bc3, n);

    // deterministic two-pass batchnorm stats + head
    k_sum_mean<<<256, 256>>>(bufB, n, part);
    k_reduce_mean<<<1, 64>>>(part, 256, n, stats);
    k_sum_var<<<256, 256>>>(bufB, n, stats, part);
    k_reduce_var<<<1, 64>>>(part, 256, n, gamma, beta, stats);
    k_final<<<ablocks, 256>>>((const float2*)bufB, stats, W2, b2, W3, b3,
                              (float*)d_out, n);
}

// round 4
// speedup vs baseline: 1.0939x; 1.0520x over previous
#include <cuda_runtime.h>
#include <cuda_bf16.h>

typedef unsigned long long ull;

#define F_IN   512
#define D_EMB  128
#define D_HID  64
#define N_CLS  32
#define MAXN   100000
#define MAXE   1600000

// ---------------- device scratch (no allocation allowed) ----------------
__device__ float g_bufA[MAXN * D_HID];
__device__ float g_bufB[MAXN * D_HID];
__device__ int   g_deg [MAXN + 2];
__device__ int   g_incl[MAXN + 2];
__device__ int   g_bsum[512];
__device__ int   g_rp  [MAXN + 2];
__device__ int   g_cur [MAXN + 2];
__device__ int   g_col [MAXE + 2];
__device__ float g_stats[256];
__device__ float g_part[256 * 64];

// ---------------- f32x2 packed-FMA helpers ----------------
__device__ __forceinline__ ull dup2(float v) {
    ull r; asm("mov.b64 %0, {%1, %1};" : "=l"(r) : "f"(v)); return r;
}
__device__ __forceinline__ void ffma2(ull &acc, ull a, ull b) {
    asm("fma.rn.f32x2 %0, %1, %2, %0;" : "+l"(acc) : "l"(a), "l"(b));
}
__device__ __forceinline__ float2 unpack2(ull v) {
    float2 r; asm("mov.b64 {%0, %1}, %2;" : "=f"(r.x), "=f"(r.y) : "l"(v)); return r;
}

// =====================================================================
// K1: g1 = relu(x @ W1 + b1) @ Wc1      [n x 64]
// 2 CTAs/SM (launch_bounds cap 128 regs) for latency hiding.
// =====================================================================
#define LIN1_HSS 132
#define LIN1_SMEM ((D_EMB*D_HID + 128*LIN1_HSS) * 4)

__device__ __forceinline__ void l1_fetchA(const float* __restrict__ x, int n,
                                          int row0, int k0, int tid, float4* pa) {
    int m = tid & 127, cc = tid >> 7;
    const float4* p = (const float4*)(x + (size_t)(row0 + m) * F_IN + k0 + cc * 16);
    bool v = (row0 + m) < n;
#pragma unroll
    for (int i = 0; i < 4; i++)
        pa[i] = v ? p[i] : make_float4(0.f, 0.f, 0.f, 0.f);
}
__device__ __forceinline__ void l1_storeA(float* As, int tid, const float4* pa) {
    int m = tid & 127, cc = tid >> 7;
#pragma unroll
    for (int i = 0; i < 4; i++) {
        int kk = cc * 16 + i * 4;
        As[(kk + 0) * 128 + m] = pa[i].x;
        As[(kk + 1) * 128 + m] = pa[i].y;
        As[(kk + 2) * 128 + m] = pa[i].z;
        As[(kk + 3) * 128 + m] = pa[i].w;
    }
}
__device__ __forceinline__ void l1_fetchB(const float* __restrict__ W1,
                                          int k0, int tid, float4* pb) {
    const float4* p = (const float4*)(W1 + (size_t)k0 * D_EMB);
#pragma unroll
    for (int i = 0; i < 4; i++) pb[i] = p[tid + i * 256];
}
__device__ __forceinline__ void l1_storeB(float* Bs, int tid, const float4* pb) {
#pragma unroll
    for (int i = 0; i < 4; i++) ((float4*)Bs)[tid + i * 256] = pb[i];
}

__global__ void __launch_bounds__(256, 2) k_lin1(
    const float* __restrict__ x, const float* __restrict__ W1,
    const float* __restrict__ b1, const float* __restrict__ Wc1,
    float* __restrict__ g1, int n)
{
    extern __shared__ float smem[];
    float* WcS = smem;
    float* As  = smem + D_EMB * D_HID;
    float* Bs  = As + 32 * 128;
    float* Hs  = smem + D_EMB * D_HID;

    const int tid = threadIdx.x;
    const int tx = tid & 15, ty = tid >> 4;
    const int row0 = blockIdx.x * 128;

    {
        const float4* s = (const float4*)Wc1;
        float4* d = (float4*)WcS;
#pragma unroll
        for (int i = 0; i < 8; i++) d[tid + i * 256] = s[tid + i * 256];
    }

    ull acc[4][8];
#pragma unroll
    for (int p = 0; p < 4; p++)
#pragma unroll
        for (int j = 0; j < 8; j++) acc[p][j] = 0ull;

    float4 pa[4], pb[4];
    l1_fetchA(x, n, row0, 0, tid, pa);
    l1_fetchB(W1, 0, tid, pb);
    l1_storeA(As, tid, pa);
    l1_storeB(Bs, tid, pb);
    __syncthreads();

    for (int kt = 0; kt < F_IN / 32; kt++) {
        if (kt + 1 < F_IN / 32) {
            l1_fetchA(x, n, row0, (kt + 1) * 32, tid, pa);
            l1_fetchB(W1, (kt + 1) * 32, tid, pb);
        }
#pragma unroll 8
        for (int kk = 0; kk < 32; kk++) {
            const double2 a01 = *(const double2*)(As + kk * 128 + ty * 8);
            const double2 a23 = *(const double2*)(As + kk * 128 + ty * 8 + 4);
            ull ap[4] = { __double_as_longlong(a01.x), __double_as_longlong(a01.y),
                          __double_as_longlong(a23.x), __double_as_longlong(a23.y) };
            // group 1: B cols tx*8..tx*8+3  (halves live bd regs vs 8-wide)
            {
                const float4 bl = *(const float4*)(Bs + kk * 128 + tx * 8);
                ull bd0 = dup2(bl.x), bd1 = dup2(bl.y), bd2 = dup2(bl.z), bd3 = dup2(bl.w);
#pragma unroll
                for (int p = 0; p < 4; p++) {
                    ffma2(acc[p][0], ap[p], bd0);
                    ffma2(acc[p][1], ap[p], bd1);
                    ffma2(acc[p][2], ap[p], bd2);
                    ffma2(acc[p][3], ap[p], bd3);
                }
            }
            // group 2: B cols tx*8+4..tx*8+7
            {
                const float4 bh = *(const float4*)(Bs + kk * 128 + tx * 8 + 4);
                ull bd4 = dup2(bh.x), bd5 = dup2(bh.y), bd6 = dup2(bh.z), bd7 = dup2(bh.w);
#pragma unroll
                for (int p = 0; p < 4; p++) {
                    ffma2(acc[p][4], ap[p], bd4);
                    ffma2(acc[p][5], ap[p], bd5);
                    ffma2(acc[p][6], ap[p], bd6);
                    ffma2(acc[p][7], ap[p], bd7);
                }
            }
        }
        __syncthreads();
        if (kt + 1 < F_IN / 32) {
            l1_storeA(As, tid, pa);
            l1_storeB(Bs, tid, pb);
            __syncthreads();
        }
    }

    float bb[8];
    {
        float4 b1l = ((const float4*)b1)[tx * 2];
        float4 b1h = ((const float4*)b1)[tx * 2 + 1];
        bb[0] = b1l.x; bb[1] = b1l.y; bb[2] = b1l.z; bb[3] = b1l.w;
        bb[4] = b1h.x; bb[5] = b1h.y; bb[6] = b1h.z; bb[7] = b1h.w;
    }
#pragma unroll
    for (int p = 0; p < 4; p++) {
        float r0[8], r1[8];
#pragma unroll
        for (int j = 0; j < 8; j++) {
            float2 v = unpack2(acc[p][j]);
            r0[j] = fmaxf(v.x + bb[j], 0.f);
            r1[j] = fmaxf(v.y + bb[j], 0.f);
        }
        int m0 = ty * 8 + 2 * p;
        *(float4*)(Hs + m0 * LIN1_HSS + tx * 8)           = make_float4(r0[0], r0[1], r0[2], r0[3]);
        *(float4*)(Hs + m0 * LIN1_HSS + tx * 8 + 4)       = make_float4(r0[4], r0[5], r0[6], r0[7]);
        *(float4*)(Hs + (m0 + 1) * LIN1_HSS + tx * 8)     = make_float4(r1[0], r1[1], r1[2], r1[3]);
        *(float4*)(Hs + (m0 + 1) * LIN1_HSS + tx * 8 + 4) = make_float4(r1[4], r1[5], r1[6], r1[7]);
    }
    __syncthreads();

    const int rg = ty, cg = tx;
    ull o[8][2];
#pragma unroll
    for (int i = 0; i < 8; i++) { o[i][0] = 0ull; o[i][1] = 0ull; }

#pragma unroll 4
    for (int em4 = 0; em4 < D_EMB; em4 += 4) {
        double2 bp0 = *(const double2*)(WcS + (em4 + 0) * D_HID + cg * 4);
        double2 bp1 = *(const double2*)(WcS + (em4 + 1) * D_HID + cg * 4);
        double2 bp2 = *(const double2*)(WcS + (em4 + 2) * D_HID + cg * 4);
        double2 bp3 = *(const double2*)(WcS + (em4 + 3) * D_HID + cg * 4);
#pragma unroll
        for (int i = 0; i < 8; i++) {
            float4 a4 = *(const float4*)(Hs + (rg * 8 + i) * LIN1_HSS + em4);
            ull a;
            a = dup2(a4.x);
            ffma2(o[i][0], a, __double_as_longlong(bp0.x));
            ffma2(o[i][1], a, __double_as_longlong(bp0.y));
            a = dup2(a4.y);
            ffma2(o[i][0], a, __double_as_longlong(bp1.x));
            ffma2(o[i][1], a, __double_as_longlong(bp1.y));
            a = dup2(a4.z);
            ffma2(o[i][0], a, __double_as_longlong(bp2.x));
            ffma2(o[i][1], a, __double_as_longlong(bp2.y));
            a = dup2(a4.w);
            ffma2(o[i][0], a, __double_as_longlong(bp3.x));
            ffma2(o[i][1], a, __double_as_longlong(bp3.y));
        }
    }
#pragma unroll
    for (int i = 0; i < 8; i++) {
        int m = rg * 8 + i;
        if (row0 + m < n) {
            float2 lo = unpack2(o[i][0]);
            float2 hi = unpack2(o[i][1]);
            *(float4*)(g1 + (size_t)(row0 + m) * D_HID + cg * 4) =
                make_float4(lo.x, lo.y, hi.x, hi.y);
        }
    }
}

// =====================================================================
// CSR build
// =====================================================================
__global__ void k_zero_int(int* p, int n) {
    int i = blockIdx.x * blockDim.x + threadIdx.x;
    if (i < n) p[i] = 0;
}
__global__ void k_hist(const int* __restrict__ dst, int E, int* __restrict__ deg) {
    int e = blockIdx.x * blockDim.x + threadIdx.x;
    if (e < E) atomicAdd(&deg[dst[e]], 1);
}
__global__ void k_scan1(const int* __restrict__ in, int n,
                        int* __restrict__ incl, int* __restrict__ bsum) {
    __shared__ int s[512];
    int i = blockIdx.x * 512 + threadIdx.x;
    s[threadIdx.x] = (i < n) ? in[i] : 0;
    __syncthreads();
#pragma unroll
    for (int off = 1; off < 512; off <<= 1) {
        int t = (threadIdx.x >= off) ? s[threadIdx.x - off] : 0;
        __syncthreads();
        s[threadIdx.x] += t;
        __syncthreads();
    }
    if (i < n) incl[i] = s[threadIdx.x];
    if (bsum && threadIdx.x == 511) bsum[blockIdx.x] = s[511];
}
__global__ void k_scan3(const int* __restrict__ incl, const int* __restrict__ bsum,
                        const int* __restrict__ deg, int* __restrict__ rp,
                        int* __restrict__ cur, int n) {
    int i = blockIdx.x * blockDim.x + threadIdx.x;
    if (i >= n) return;
    int b = i >> 9;
    int off = (b > 0) ? bsum[b - 1] : 0;
    int v = incl[i] + off;
    rp[i + 1] = v;
    cur[i] = v - deg[i];
    if (i == 0) rp[0] = 0;
}
__global__ void k_fill(const int* __restrict__ src, const int* __restrict__ dst,
                       int E, int* __restrict__ cur, int* __restrict__ col) {
    int e = blockIdx.x * blockDim.x + threadIdx.x;
    if (e >= E) return;
    int pos = atomicAdd(&cur[dst[e]], 1);
    col[pos] = src[e];
}

// =====================================================================
// Canonicalize CSR segment order (determinism)
// =====================================================================
__global__ void __launch_bounds__(256) k_sortseg(
    const int* __restrict__ rp, int* __restrict__ col, int n)
{
    __shared__ int sbuf[8][1024];
    int lane = threadIdx.x & 31, w = threadIdx.x >> 5;
    int node = blockIdx.x * 8 + w;
    if (node >= n) return;
    int beg = rp[node], end = rp[node + 1];
    int d = end - beg;
    if (d <= 1) return;

    if (d <= 32) {
        int v = (lane < d) ? col[beg + lane] : 0x7fffffff;
#pragma unroll
        for (int k = 2; k <= 32; k <<= 1) {
#pragma unroll
            for (int j = k >> 1; j > 0; j >>= 1) {
                int other = __shfl_xor_sync(0xffffffffu, v, j);
                bool dirUp = ((lane & k) == 0);
                bool takeMin = (((lane & j) == 0) == dirUp);
                v = takeMin ? min(v, other) : max(v, other);
            }
        }
        if (lane < d) col[beg + lane] = v;
    } else if (d <= 1024) {
        int* s = sbuf[w];
        for (int i = lane; i < d; i += 32) s[i] = col[beg + i];
        __syncwarp();
        for (int ph = 0; ph < d; ph++) {
            int start = ph & 1;
            for (int i = start + 2 * lane; i + 1 < d; i += 64) {
                int a = s[i], b = s[i + 1];
                if (a > b) { s[i] = b; s[i + 1] = a; }
            }
            __syncwarp();
        }
        for (int i = lane; i < d; i += 32) col[beg + i] = s[i];
    } else {
        if (lane == 0) {
            for (int i = beg + 1; i < end; i++) {
                int key = col[i];
                int j = i - 1;
                while (j >= beg && col[j] > key) { col[j + 1] = col[j]; j--; }
                col[j + 1] = key;
            }
        }
    }
}

// =====================================================================
// Aggregation: warp per node, MLP=8 gather.
// =====================================================================
__device__ __forceinline__ void warp_agg(const float2* __restrict__ gin,
                                         const int* __restrict__ col,
                                         int beg, int end, int lane,
                                         float& ax, float& ay) {
    ax = 0.f; ay = 0.f;
    for (int e0 = beg; e0 < end; e0 += 32) {
        int idx = e0 + lane;
        int c = (idx < end) ? __ldg(&col[idx]) : 0;
        int cnt = min(32, end - e0);
        int j = 0;
        for (; j + 8 <= cnt; j += 8) {
            int s0 = __shfl_sync(0xffffffffu, c, j);
            int s1 = __shfl_sync(0xffffffffu, c, j + 1);
            int s2 = __shfl_sync(0xffffffffu, c, j + 2);
            int s3 = __shfl_sync(0xffffffffu, c, j + 3);
            int s4 = __shfl_sync(0xffffffffu, c, j + 4);
            int s5 = __shfl_sync(0xffffffffu, c, j + 5);
            int s6 = __shfl_sync(0xffffffffu, c, j + 6);
            int s7 = __shfl_sync(0xffffffffu, c, j + 7);
            float2 v0 = gin[s0 * 32 + lane];
            float2 v1 = gin[s1 * 32 + lane];
            float2 v2 = gin[s2 * 32 + lane];
            float2 v3 = gin[s3 * 32 + lane];
            float2 v4 = gin[s4 * 32 + lane];
            float2 v5 = gin[s5 * 32 + lane];
            float2 v6 = gin[s6 * 32 + lane];
            float2 v7 = gin[s7 * 32 + lane];
            ax += v0.x; ay += v0.y;
            ax += v1.x; ay += v1.y;
            ax += v2.x; ay += v2.y;
            ax += v3.x; ay += v3.y;
            ax += v4.x; ay += v4.y;
            ax += v5.x; ay += v5.y;
            ax += v6.x; ay += v6.y;
            ax += v7.x; ay += v7.y;
        }
        for (; j < cnt; j++) {
            int s = __shfl_sync(0xffffffffu, c, j);
            float2 v = gin[s * 32 + lane];
            ax += v.x; ay += v.y;
        }
    }
}

#define HT_STRIDE 10
__global__ void __launch_bounds__(256) k_agg_mm(
    const float2* __restrict__ gin, float2* __restrict__ gout,
    const int* __restrict__ rp, const int* __restrict__ col,
    const float* __restrict__ bias, const float* __restrict__ W, int n)
{
    __shared__ float Ws[D_HID * D_HID];
    __shared__ float hT[D_HID][HT_STRIDE];
    int tid = threadIdx.x;
    {
        const float4* s = (const float4*)W;
        float4* d = (float4*)Ws;
#pragma unroll
        for (int i = 0; i < 4; i++) d[tid + i * 256] = s[tid + i * 256];
    }
    int lane = tid & 31, w = tid >> 5;
    int node = blockIdx.x * 8 + w;
    if (node < n) {
        int beg = rp[node], end = rp[node + 1];
        float ax, ay;
        warp_agg(gin, col, beg, end, lane, ax, ay);
        float inv = 1.f / fmaxf((float)(end - beg), 1.f);
        float b0 = bias[2 * lane], b1v = bias[2 * lane + 1];
        hT[2 * lane][w]     = fmaxf(fmaf(ax, inv, b0), 0.f);
        hT[2 * lane + 1][w] = fmaxf(fmaf(ay, inv, b1v), 0.f);
    }
    __syncthreads();
    if (w < 4) {
        int n0 = blockIdx.x * 8 + 2 * w;
        if (n0 < n) {
            int n1 = n0 + 1;
            const float2* wsp = (const float2*)Ws;
            ull oXe = 0ull, oXo = 0ull, oYe = 0ull, oYo = 0ull;
#pragma unroll
            for (int k = 0; k < D_HID; k += 2) {
                ull h0 = *(const ull*)(&hT[k][2 * w]);
                ull h1 = *(const ull*)(&hT[k + 1][2 * w]);
                float2 w0 = wsp[k * 32 + lane];
                float2 w1 = wsp[(k + 1) * 32 + lane];
                ffma2(oXe, h0, dup2(w0.x));
                ffma2(oYe, h0, dup2(w0.y));
                ffma2(oXo, h1, dup2(w1.x));
                ffma2(oYo, h1, dup2(w1.y));
            }
            float2 xe = unpack2(oXe), xo = unpack2(oXo);
            float2 ye = unpack2(oYe), yo = unpack2(oYo);
            gout[n0 * 32 + lane] = make_float2(xe.x + xo.x, ye.x + yo.x);
            if (n1 < n)
                gout[n1 * 32 + lane] = make_float2(xe.y + xo.y, ye.y + yo.y);
        }
    }
}

__global__ void __launch_bounds__(256) k_agg_final(
    const float2* __restrict__ gin, float2* __restrict__ gout,
    const int* __restrict__ rp, const int* __restrict__ col,
    const float* __restrict__ bias, int n)
{
    int tid = threadIdx.x;
    int lane = tid & 31, w = tid >> 5;
    int node = blockIdx.x * 8 + w;
    if (node >= n) return;
    int beg = rp[node], end = rp[node + 1];
    float ax, ay;
    warp_agg(gin, col, beg, end, lane, ax, ay);
    float inv = 1.f / fmaxf((float)(end - beg), 1.f);
    float b0 = bias[2 * lane], b1v = bias[2 * lane + 1];
    float2 h;
    h.x = fmaxf(fmaf(ax, inv, b0), 0.f);
    h.y = fmaxf(fmaf(ay, inv, b1v), 0.f);
    gout[node * 32 + lane] = h;
}

// =====================================================================
// Deterministic two-pass batchnorm statistics
// =====================================================================
__global__ void __launch_bounds__(256) k_sum_mean(
    const float* __restrict__ h, int n, float* __restrict__ part)
{
    __shared__ float sb[4][64];
    int f = threadIdx.x & 63;
    int ty = threadIdx.x >> 6;
    float s = 0.f;
    for (int r = blockIdx.x * 4 + ty; r < n; r += gridDim.x * 4)
        s += h[(size_t)r * 64 + f];
    sb[ty][f] = s;
    __syncthreads();
    if (threadIdx.x < 64) {
        float t = ((sb[0][f] + sb[1][f]) + sb[2][f]) + sb[3][f];
        part[blockIdx.x * 64 + f] = t;
    }
}
__global__ void k_reduce_mean(const float* __restrict__ part, int nb, int n,
                              float* __restrict__ stats)
{
    int f = threadIdx.x;
    float s = 0.f;
    for (int b = 0; b < nb; b++) s += part[b * 64 + f];
    stats[f] = s / (float)n;
}
__global__ void __launch_bounds__(256) k_sum_var(
    const float* __restrict__ h, int n, const float* __restrict__ stats,
    float* __restrict__ part)
{
    __shared__ float sb[4][64];
    int f = threadIdx.x & 63;
    int ty = threadIdx.x >> 6;
    float mean = stats[f];
    float s = 0.f;
    for (int r = blockIdx.x * 4 + ty; r < n; r += gridDim.x * 4) {
        float d = h[(size_t)r * 64 + f] - mean;
        s = fmaf(d, d, s);
    }
    sb[ty][f] = s;
    __syncthreads();
    if (threadIdx.x < 64) {
        float t = ((sb[0][f] + sb[1][f]) + sb[2][f]) + sb[3][f];
        part[blockIdx.x * 64 + f] = t;
    }
}
__global__ void k_reduce_var(const float* __restrict__ part, int nb, int n,
                             const float* __restrict__ gamma,
                             const float* __restrict__ beta,
                             float* __restrict__ stats)
{
    int f = threadIdx.x;
    float s = 0.f;
    for (int b = 0; b < nb; b++) s += part[b * 64 + f];
    float var = s / (float)n;
    float mean = stats[f];
    float rstd = rsqrtf(var + 1e-5f);
    float sc = rstd * gamma[f];
    stats[128 + f] = sc;
    stats[192 + f] = beta[f] - mean * sc;
}

// =====================================================================
// Final head
// =====================================================================
__global__ void __launch_bounds__(256) k_final(
    const float2* __restrict__ h3, const float* __restrict__ stats,
    const float* __restrict__ W2, const float* __restrict__ b2,
    const float* __restrict__ W3, const float* __restrict__ b3,
    float* __restrict__ out, int n)
{
    __shared__ float W2s[D_HID * N_CLS];
    __shared__ float W3s[N_CLS * N_CLS];
    __shared__ float hb[8][D_HID];
    __shared__ float tb[8][N_CLS];
    int tid = threadIdx.x;
    {
        const float4* s2 = (const float4*)W2;
        float4* d2 = (float4*)W2s;
        d2[tid] = s2[tid];
        d2[tid + 256] = s2[tid + 256];
        ((float4*)W3s)[tid] = ((const float4*)W3)[tid];
    }
    __syncthreads();
    int lane = tid & 31, w = tid >> 5;
    int node = blockIdx.x * 8 + w;
    if (node >= n) return;
    float2 h = h3[node * 32 + lane];
    float s0 = stats[128 + 2 * lane], s1 = stats[128 + 2 * lane + 1];
    float t0 = stats[192 + 2 * lane], t1 = stats[192 + 2 * lane + 1];
    hb[w][2 * lane]     = fmaf(h.x, s0, t0);
    hb[w][2 * lane + 1] = fmaf(h.y, s1, t1);
    __syncwarp();
    float t = b2[lane];
#pragma unroll
    for (int k = 0; k < D_HID; k++) t = fmaf(hb[w][k], W2s[k * 32 + lane], t);
    t = fmaxf(t, 0.f);
    tb[w][lane] = t;
    __syncwarp();
    float o = b3[lane];
#pragma unroll
    for (int k = 0; k < N_CLS; k++) o = fmaf(tb[w][k], W3s[k * 32 + lane], o);
    out[(size_t)node * 32 + lane] = o;
}

// =====================================================================
// launch  (k_lin1 kept in the ncu-profiled slot #4)
// =====================================================================
extern "C" void kernel_launch(void* const* d_in, const int* in_sizes, int n_in,
                              void* d_out, int out_size) {
    const float* x     = (const float*)d_in[0];
    const float* W1    = (const float*)d_in[1];
    const float* b1    = (const float*)d_in[2];
    const float* Wc1   = (const float*)d_in[3];
    const float* bc1   = (const float*)d_in[4];
    const float* Wc2   = (const float*)d_in[5];
    const float* bc2   = (const float*)d_in[6];
    const float* Wc3   = (const float*)d_in[7];
    const float* bc3   = (const float*)d_in[8];
    const float* gamma = (const float*)d_in[9];
    const float* beta  = (const float*)d_in[10];
    const float* W2    = (const float*)d_in[11];
    const float* b2    = (const float*)d_in[12];
    const float* W3    = (const float*)d_in[13];
    const float* b3    = (const float*)d_in[14];
    const int*   ei    = (const int*)d_in[15];

    int n = in_sizes[0] / F_IN;
    int E = in_sizes[15] / 2;
    const int* src = ei;
    const int* dst = ei + E;

    float *bufA, *bufB, *stats, *part;
    int *deg, *incl, *bsum, *rp, *cur, *colb;
    cudaGetSymbolAddress((void**)&bufA, g_bufA);
    cudaGetSymbolAddress((void**)&bufB, g_bufB);
    cudaGetSymbolAddress((void**)&stats, g_stats);
    cudaGetSymbolAddress((void**)&part, g_part);
    cudaGetSymbolAddress((void**)&deg, g_deg);
    cudaGetSymbolAddress((void**)&incl, g_incl);
    cudaGetSymbolAddress((void**)&bsum, g_bsum);
    cudaGetSymbolAddress((void**)&rp, g_rp);
    cudaGetSymbolAddress((void**)&cur, g_cur);
    cudaGetSymbolAddress((void**)&colb, g_col);

    cudaFuncSetAttribute(k_lin1, cudaFuncAttributeMaxDynamicSharedMemorySize, LIN1_SMEM);

    int NB = (n + 511) / 512;
    int ablocks = (n + 7) / 8;

    // CSR-prefix kernels first; k_lin1 in launch slot #4 (ncu capture slot).
    k_zero_int<<<(n + 255) / 256, 256>>>(deg, n);
    k_hist<<<(E + 255) / 256, 256>>>(dst, E, deg);
    k_scan1<<<NB, 512>>>(deg, n, incl, bsum);
    k_lin1<<<(n + 127) / 128, 256, LIN1_SMEM>>>(x, W1, b1, Wc1, bufA, n);
    k_scan1<<<1, 512>>>(bsum, NB, bsum, (int*)0);
    k_scan3<<<(n + 255) / 256, 256>>>(incl, bsum, deg, rp, cur, n);
    k_fill<<<(E + 255) / 256, 256>>>(src, dst, E, cur, colb);
    k_sortseg<<<ablocks, 256>>>(rp, colb, n);

    // conv1 (+Wc2 pre-applied), conv2 (+Wc3 pre-applied), conv3
    k_agg_mm<<<ablocks, 256>>>((const float2*)bufA, (float2*)bufB, rp, colb, bc1, Wc2, n);
    k_agg_mm<<<ablocks, 256>>>((const float2*)bufB, (float2*)bufA, rp, colb, bc2, Wc3, n);
    k_agg_final<<<ablocks, 256>>>((const float2*)bufA, (float2*)bufB, rp, colb, bc3, n);

    // deterministic two-pass batchnorm stats + head
    k_sum_mean<<<256, 256>>>(bufB, n, part);
    k_reduce_mean<<<1, 64>>>(part, 256, n, stats);
    k_sum_var<<<256, 256>>>(bufB, n, stats, part);
    k_reduce_var<<<1, 64>>>(part, 256, n, gamma, beta, stats);
    k_final<<<ablocks, 256>>>((const float2*)bufB, stats, W2, b2, W3, b3,
                              (float*)d_out, n);
}

// round 6
// speedup vs baseline: 1.2112x; 1.1072x over previous
#include <cuda_runtime.h>
#include <cuda_bf16.h>
#include <cstdint>

typedef unsigned long long ull;

#define F_IN   512
#define D_EMB  128
#define D_HID  64
#define N_CLS  32
#define MAXN   100000
#define MAXE   1600000

// ---------------- device scratch (no allocation allowed) ----------------
__device__ float g_bufA[MAXN * D_HID];
__device__ float g_bufB[MAXN * D_HID];
__device__ int   g_deg [MAXN + 2];
__device__ int   g_incl[MAXN + 2];
__device__ int   g_bsum[512];
__device__ int   g_rp  [MAXN + 2];
__device__ int   g_cur [MAXN + 2];
__device__ int   g_col [MAXE + 2];
__device__ float g_stats[256];
__device__ float g_part[256 * 64];
__device__ float g_W1T_hi[D_EMB * F_IN];
__device__ float g_W1T_lo[D_EMB * F_IN];

// ---------------- helpers ----------------
__device__ __forceinline__ ull dup2(float v) {
    ull r; asm("mov.b64 %0, {%1, %1};" : "=l"(r) : "f"(v)); return r;
}
__device__ __forceinline__ void ffma2(ull &acc, ull a, ull b) {
    asm("fma.rn.f32x2 %0, %1, %2, %0;" : "+l"(acc) : "l"(a), "l"(b));
}
__device__ __forceinline__ float2 unpack2(ull v) {
    float2 r; asm("mov.b64 {%0, %1}, %2;" : "=f"(r.x), "=f"(r.y) : "l"(v)); return r;
}
__device__ __forceinline__ float tf32r(float v) {
    uint32_t r; asm("cvt.rna.tf32.f32 %0, %1;" : "=r"(r) : "f"(v));
    return __uint_as_float(r);
}

// portable tensor-core MMA: m16n8k8 tf32 (sm_80+; valid on compute_103)
#define MMA_TF32(c, a, b)                                                       \
    asm volatile(                                                               \
        "mma.sync.aligned.m16n8k8.row.col.f32.tf32.tf32.f32 "                   \
        "{%0,%1,%2,%3}, {%4,%5,%6,%7}, {%8,%9}, {%0,%1,%2,%3};"                 \
        : "+f"((c)[0]), "+f"((c)[1]), "+f"((c)[2]), "+f"((c)[3])                \
        : "r"(__float_as_uint((a)[0])), "r"(__float_as_uint((a)[1])),           \
          "r"(__float_as_uint((a)[2])), "r"(__float_as_uint((a)[3])),           \
          "r"(__float_as_uint((b)[0])), "r"(__float_as_uint((b)[1])))

// =====================================================================
// k_prepW: W1[512][128] -> W1T_hi/lo[128][512] (transpose + tf32 split)
// =====================================================================
__global__ void __launch_bounds__(256) k_prepW(
    const float* __restrict__ W1, float* __restrict__ hiT, float* __restrict__ loT)
{
    __shared__ float ts[32][33];
    int kt = blockIdx.x & 15, nt = blockIdx.x >> 4;
    int tx = threadIdx.x & 31, ty = threadIdx.x >> 5;   // ty 0..7
#pragma unroll
    for (int r = 0; r < 4; r++) {
        int k = kt * 32 + ty + r * 8;
        ts[ty + r * 8][tx] = W1[k * D_EMB + nt * 32 + tx];
    }
    __syncthreads();
#pragma unroll
    for (int r = 0; r < 4; r++) {
        int nn = nt * 32 + ty + r * 8;
        float v = ts[tx][ty + r * 8];
        float hi = tf32r(v);
        float lo = tf32r(v - hi);
        hiT[nn * F_IN + kt * 32 + tx] = hi;
        loT[nn * F_IN + kt * 32 + tx] = lo;
    }
}

// =====================================================================
// k_lin1_mma: g1 = relu(x @ W1 + b1) @ Wc1 via 3xTF32 mma.sync
// 512 threads; CTA tile 128x128; 16 warps in 4x4 grid, warp tile 32x32.
// smem layout (floats):
//   [0 .. 8192)              WcS  (Wc1, 128x64)
//   [8192 .. 8192+4*4608)    As_hi | As_lo | Bs_hi | Bs_lo  (128x36 each)
//                            (reused as Hs[128][132] in the epilogue)
//   [26624 .. 26752)         b1s
// =====================================================================
#define TS36   36
#define SMF_WC 8192
#define SMF_T  (SMF_WC)                     // tiles start (float idx) after WcS
#define MMA_SMEM ((8192 + 4 * 128 * TS36 + 128) * 4)
#define LIN1_HSS 132

__global__ void __launch_bounds__(512) k_lin1_mma(
    const float* __restrict__ x, const float* __restrict__ Whi,
    const float* __restrict__ Wlo, const float* __restrict__ b1,
    const float* __restrict__ Wc1, float* __restrict__ g1, int n)
{
    extern __shared__ float sm[];
    float* WcS   = sm;
    float* As_hi = sm + 8192;
    float* As_lo = As_hi + 128 * TS36;
    float* Bs_hi = As_lo + 128 * TS36;
    float* Bs_lo = Bs_hi + 128 * TS36;
    float* Hs    = As_hi;                    // epilogue overlay
    float* b1s   = sm + 8192 + 4 * 128 * TS36;

    const int tid  = threadIdx.x;
    const int wid  = tid >> 5, lane = tid & 31;
    const int gid  = lane >> 2, tig = lane & 3;
    const int wm   = wid & 3, wn = wid >> 2;       // 4x4 warp grid
    const int row0 = blockIdx.x * 128;

    // load Wc1 + b1 (persist through mainloop)
    {
        const float4* s = (const float4*)Wc1;
        float4* d = (float4*)WcS;
#pragma unroll
        for (int i = 0; i < 4; i++) d[tid + i * 512] = s[tid + i * 512];
        if (tid < 128) b1s[tid] = b1[tid];
    }

    float c[2][4][4];
#pragma unroll
    for (int am = 0; am < 2; am++)
#pragma unroll
        for (int an = 0; an < 4; an++)
#pragma unroll
            for (int q = 0; q < 4; q++) c[am][an][q] = 0.f;

    // prefetch registers
    float4 xa[2], wbh[2], wbl[2];
    const int am_ld = (tid + 0) >> 3;             // row for A loads (idx>>3)
    // fetch chunk kc into regs
    auto FETCH = [&](int kc) {
#pragma unroll
        for (int it = 0; it < 2; it++) {
            int idx = tid + it * 512;
            int m = idx >> 3, j4 = idx & 7;
            bool v = (row0 + m) < n;
            xa[it] = v ? *(const float4*)(x + (size_t)(row0 + m) * F_IN + kc * 32 + j4 * 4)
                       : make_float4(0.f, 0.f, 0.f, 0.f);
            wbh[it] = *(const float4*)(Whi + (size_t)m * F_IN + kc * 32 + j4 * 4);
            wbl[it] = *(const float4*)(Wlo + (size_t)m * F_IN + kc * 32 + j4 * 4);
        }
    };
    auto STORE = [&]() {
#pragma unroll
        for (int it = 0; it < 2; it++) {
            int idx = tid + it * 512;
            int m = idx >> 3, j4 = idx & 7;
            float4 a = xa[it];
            float4 hi, lo;
            hi.x = tf32r(a.x); lo.x = tf32r(a.x - hi.x);
            hi.y = tf32r(a.y); lo.y = tf32r(a.y - hi.y);
            hi.z = tf32r(a.z); lo.z = tf32r(a.z - hi.z);
            hi.w = tf32r(a.w); lo.w = tf32r(a.w - hi.w);
            int off = m * TS36 + j4 * 4;
            *(float4*)(As_hi + off) = hi;
            *(float4*)(As_lo + off) = lo;
            *(float4*)(Bs_hi + off) = wbh[it];
            *(float4*)(Bs_lo + off) = wbl[it];
        }
    };
    (void)am_ld;

    FETCH(0);
    STORE();
    __syncthreads();

    for (int kc = 0; kc < 16; kc++) {
        if (kc + 1 < 16) FETCH(kc + 1);
#pragma unroll
        for (int ks = 0; ks < 4; ks++) {
            const int k0 = ks * 8 + tig, k1 = ks * 8 + tig + 4;
            float ah[2][4], al[2][4];
#pragma unroll
            for (int am = 0; am < 2; am++) {
                int ra = (wm * 32 + am * 16 + gid) * TS36;
                ah[am][0] = As_hi[ra + k0];
                ah[am][1] = As_hi[ra + 8 * TS36 + k0];
                ah[am][2] = As_hi[ra + k1];
                ah[am][3] = As_hi[ra + 8 * TS36 + k1];
                al[am][0] = As_lo[ra + k0];
                al[am][1] = As_lo[ra + 8 * TS36 + k0];
                al[am][2] = As_lo[ra + k1];
                al[am][3] = As_lo[ra + 8 * TS36 + k1];
            }
#pragma unroll
            for (int an = 0; an < 4; an++) {
                int rb = (wn * 32 + an * 8 + gid) * TS36;
                float bh[2], bl[2];
                bh[0] = Bs_hi[rb + k0];
                bh[1] = Bs_hi[rb + k1];
                bl[0] = Bs_lo[rb + k0];
                bl[1] = Bs_lo[rb + k1];
#pragma unroll
                for (int am = 0; am < 2; am++) {
                    MMA_TF32(c[am][an], ah[am], bh);
                    MMA_TF32(c[am][an], ah[am], bl);
                    MMA_TF32(c[am][an], al[am], bh);
                }
            }
        }
        __syncthreads();
        if (kc + 1 < 16) {
            STORE();
            __syncthreads();
        }
    }

    // ---- epilogue 1: bias + relu, stage into Hs[128][132] ----
#pragma unroll
    for (int am = 0; am < 2; am++) {
        int r0 = wm * 32 + am * 16 + gid;
#pragma unroll
        for (int an = 0; an < 4; an++) {
            int col = wn * 32 + an * 8 + 2 * tig;
            float bb0 = b1s[col], bb1 = b1s[col + 1];
            float2 lo2 = make_float2(fmaxf(c[am][an][0] + bb0, 0.f),
                                     fmaxf(c[am][an][1] + bb1, 0.f));
            float2 hi2 = make_float2(fmaxf(c[am][an][2] + bb0, 0.f),
                                     fmaxf(c[am][an][3] + bb1, 0.f));
            *(float2*)(Hs + r0 * LIN1_HSS + col)       = lo2;
            *(float2*)(Hs + (r0 + 8) * LIN1_HSS + col) = hi2;
        }
    }
    __syncthreads();

    // ---- epilogue 2: g1[128][64] = Hs[128][128] @ WcS[128][64] ----
    {
        int tx = tid & 15, ty = tid >> 4;       // ty 0..31 (4 rows), tx 0..15 (4 cols)
        ull o[4][2];
#pragma unroll
        for (int r = 0; r < 4; r++) { o[r][0] = 0ull; o[r][1] = 0ull; }
#pragma unroll 8
        for (int em = 0; em < D_EMB; em++) {
            double2 wp = *(const double2*)(WcS + em * D_HID + tx * 4);
            ull w0 = __double_as_longlong(wp.x);
            ull w1 = __double_as_longlong(wp.y);
#pragma unroll
            for (int r = 0; r < 4; r++) {
                ull hd = dup2(Hs[(ty * 4 + r) * LIN1_HSS + em]);
                ffma2(o[r][0], hd, w0);
                ffma2(o[r][1], hd, w1);
            }
        }
#pragma unroll
        for (int r = 0; r < 4; r++) {
            int m = ty * 4 + r;
            if (row0 + m < n) {
                float2 e = unpack2(o[r][0]), f = unpack2(o[r][1]);
                *(float4*)(g1 + (size_t)(row0 + m) * D_HID + tx * 4) =
                    make_float4(e.x, e.y, f.x, f.y);
            }
        }
    }
}

// =====================================================================
// CSR build
// =====================================================================
__global__ void k_zero_int(int* p, int n) {
    int i = blockIdx.x * blockDim.x + threadIdx.x;
    if (i < n) p[i] = 0;
}
__global__ void k_hist(const int* __restrict__ dst, int E, int* __restrict__ deg) {
    int e = blockIdx.x * blockDim.x + threadIdx.x;
    if (e < E) atomicAdd(&deg[dst[e]], 1);
}
__global__ void k_scan1(const int* __restrict__ in, int n,
                        int* __restrict__ incl, int* __restrict__ bsum) {
    __shared__ int s[512];
    int i = blockIdx.x * 512 + threadIdx.x;
    s[threadIdx.x] = (i < n) ? in[i] : 0;
    __syncthreads();
#pragma unroll
    for (int off = 1; off < 512; off <<= 1) {
        int t = (threadIdx.x >= off) ? s[threadIdx.x - off] : 0;
        __syncthreads();
        s[threadIdx.x] += t;
        __syncthreads();
    }
    if (i < n) incl[i] = s[threadIdx.x];
    if (bsum && threadIdx.x == 511) bsum[blockIdx.x] = s[511];
}
__global__ void k_scan3(const int* __restrict__ incl, const int* __restrict__ bsum,
                        const int* __restrict__ deg, int* __restrict__ rp,
                        int* __restrict__ cur, int n) {
    int i = blockIdx.x * blockDim.x + threadIdx.x;
    if (i >= n) return;
    int b = i >> 9;
    int off = (b > 0) ? bsum[b - 1] : 0;
    int v = incl[i] + off;
    rp[i + 1] = v;
    cur[i] = v - deg[i];
    if (i == 0) rp[0] = 0;
}
__global__ void k_fill(const int* __restrict__ src, const int* __restrict__ dst,
                       int E, int* __restrict__ cur, int* __restrict__ col) {
    int e = blockIdx.x * blockDim.x + threadIdx.x;
    if (e >= E) return;
    int pos = atomicAdd(&cur[dst[e]], 1);
    col[pos] = src[e];
}

// =====================================================================
// Canonicalize CSR segment order (determinism)
// =====================================================================
__global__ void __launch_bounds__(256) k_sortseg(
    const int* __restrict__ rp, int* __restrict__ col, int n)
{
    __shared__ int sbuf[8][1024];
    int lane = threadIdx.x & 31, w = threadIdx.x >> 5;
    int node = blockIdx.x * 8 + w;
    if (node >= n) return;
    int beg = rp[node], end = rp[node + 1];
    int d = end - beg;
    if (d <= 1) return;

    if (d <= 32) {
        int v = (lane < d) ? col[beg + lane] : 0x7fffffff;
#pragma unroll
        for (int k = 2; k <= 32; k <<= 1) {
#pragma unroll
            for (int j = k >> 1; j > 0; j >>= 1) {
                int other = __shfl_xor_sync(0xffffffffu, v, j);
                bool dirUp = ((lane & k) == 0);
                bool takeMin = (((lane & j) == 0) == dirUp);
                v = takeMin ? min(v, other) : max(v, other);
            }
        }
        if (lane < d) col[beg + lane] = v;
    } else if (d <= 1024) {
        int* s = sbuf[w];
        for (int i = lane; i < d; i += 32) s[i] = col[beg + i];
        __syncwarp();
        for (int ph = 0; ph < d; ph++) {
            int start = ph & 1;
            for (int i = start + 2 * lane; i + 1 < d; i += 64) {
                int a = s[i], b = s[i + 1];
                if (a > b) { s[i] = b; s[i + 1] = a; }
            }
            __syncwarp();
        }
        for (int i = lane; i < d; i += 32) col[beg + i] = s[i];
    } else {
        if (lane == 0) {
            for (int i = beg + 1; i < end; i++) {
                int key = col[i];
                int j = i - 1;
                while (j >= beg && col[j] > key) { col[j + 1] = col[j]; j--; }
                col[j + 1] = key;
            }
        }
    }
}

// =====================================================================
// Aggregation: warp per node, MLP=8 gather.
// =====================================================================
__device__ __forceinline__ void warp_agg(const float2* __restrict__ gin,
                                         const int* __restrict__ col,
                                         int beg, int end, int lane,
                                         float& ax, float& ay) {
    ax = 0.f; ay = 0.f;
    for (int e0 = beg; e0 < end; e0 += 32) {
        int idx = e0 + lane;
        int c = (idx < end) ? __ldg(&col[idx]) : 0;
        int cnt = min(32, end - e0);
        int j = 0;
        for (; j + 8 <= cnt; j += 8) {
            int s0 = __shfl_sync(0xffffffffu, c, j);
            int s1 = __shfl_sync(0xffffffffu, c, j + 1);
            int s2 = __shfl_sync(0xffffffffu, c, j + 2);
            int s3 = __shfl_sync(0xffffffffu, c, j + 3);
            int s4 = __shfl_sync(0xffffffffu, c, j + 4);
            int s5 = __shfl_sync(0xffffffffu, c, j + 5);
            int s6 = __shfl_sync(0xffffffffu, c, j + 6);
            int s7 = __shfl_sync(0xffffffffu, c, j + 7);
            float2 v0 = gin[s0 * 32 + lane];
            float2 v1 = gin[s1 * 32 + lane];
            float2 v2 = gin[s2 * 32 + lane];
            float2 v3 = gin[s3 * 32 + lane];
            float2 v4 = gin[s4 * 32 + lane];
            float2 v5 = gin[s5 * 32 + lane];
            float2 v6 = gin[s6 * 32 + lane];
            float2 v7 = gin[s7 * 32 + lane];
            ax += v0.x; ay += v0.y;
            ax += v1.x; ay += v1.y;
            ax += v2.x; ay += v2.y;
            ax += v3.x; ay += v3.y;
            ax += v4.x; ay += v4.y;
            ax += v5.x; ay += v5.y;
            ax += v6.x; ay += v6.y;
            ax += v7.x; ay += v7.y;
        }
        for (; j < cnt; j++) {
            int s = __shfl_sync(0xffffffffu, c, j);
            float2 v = gin[s * 32 + lane];
            ax += v.x; ay += v.y;
        }
    }
}

#define HT_STRIDE 10
__global__ void __launch_bounds__(256) k_agg_mm(
    const float2* __restrict__ gin, float2* __restrict__ gout,
    const int* __restrict__ rp, const int* __restrict__ col,
    const float* __restrict__ bias, const float* __restrict__ W, int n)
{
    __shared__ float Ws[D_HID * D_HID];
    __shared__ float hT[D_HID][HT_STRIDE];
    int tid = threadIdx.x;
    {
        const float4* s = (const float4*)W;
        float4* d = (float4*)Ws;
#pragma unroll
        for (int i = 0; i < 4; i++) d[tid + i * 256] = s[tid + i * 256];
    }
    int lane = tid & 31, w = tid >> 5;
    int node = blockIdx.x * 8 + w;
    if (node < n) {
        int beg = rp[node], end = rp[node + 1];
        float ax, ay;
        warp_agg(gin, col, beg, end, lane, ax, ay);
        float inv = 1.f / fmaxf((float)(end - beg), 1.f);
        float b0 = bias[2 * lane], b1v = bias[2 * lane + 1];
        hT[2 * lane][w]     = fmaxf(fmaf(ax, inv, b0), 0.f);
        hT[2 * lane + 1][w] = fmaxf(fmaf(ay, inv, b1v), 0.f);
    }
    __syncthreads();
    if (w < 4) {
        int n0 = blockIdx.x * 8 + 2 * w;
        if (n0 < n) {
            int n1 = n0 + 1;
            const float2* wsp = (const float2*)Ws;
            ull oXe = 0ull, oXo = 0ull, oYe = 0ull, oYo = 0ull;
#pragma unroll
            for (int k = 0; k < D_HID; k += 2) {
                ull h0 = *(const ull*)(&hT[k][2 * w]);
                ull h1 = *(const ull*)(&hT[k + 1][2 * w]);
                float2 w0 = wsp[k * 32 + lane];
                float2 w1 = wsp[(k + 1) * 32 + lane];
                ffma2(oXe, h0, dup2(w0.x));
                ffma2(oYe, h0, dup2(w0.y));
                ffma2(oXo, h1, dup2(w1.x));
                ffma2(oYo, h1, dup2(w1.y));
            }
            float2 xe = unpack2(oXe), xo = unpack2(oXo);
            float2 ye = unpack2(oYe), yo = unpack2(oYo);
            gout[n0 * 32 + lane] = make_float2(xe.x + xo.x, ye.x + yo.x);
            if (n1 < n)
                gout[n1 * 32 + lane] = make_float2(xe.y + xo.y, ye.y + yo.y);
        }
    }
}

__global__ void __launch_bounds__(256) k_agg_final(
    const float2* __restrict__ gin, float2* __restrict__ gout,
    const int* __restrict__ rp, const int* __restrict__ col,
    const float* __restrict__ bias, int n)
{
    int tid = threadIdx.x;
    int lane = tid & 31, w = tid >> 5;
    int node = blockIdx.x * 8 + w;
    if (node >= n) return;
    int beg = rp[node], end = rp[node + 1];
    float ax, ay;
    warp_agg(gin, col, beg, end, lane, ax, ay);
    float inv = 1.f / fmaxf((float)(end - beg), 1.f);
    float b0 = bias[2 * lane], b1v = bias[2 * lane + 1];
    float2 h;
    h.x = fmaxf(fmaf(ax, inv, b0), 0.f);
    h.y = fmaxf(fmaf(ay, inv, b1v), 0.f);
    gout[node * 32 + lane] = h;
}

// =====================================================================
// Deterministic two-pass batchnorm statistics
// =====================================================================
__global__ void __launch_bounds__(256) k_sum_mean(
    const float* __restrict__ h, int n, float* __restrict__ part)
{
    __shared__ float sb[4][64];
    int f = threadIdx.x & 63;
    int ty = threadIdx.x >> 6;
    float s = 0.f;
    for (int r = blockIdx.x * 4 + ty; r < n; r += gridDim.x * 4)
        s += h[(size_t)r * 64 + f];
    sb[ty][f] = s;
    __syncthreads();
    if (threadIdx.x < 64) {
        float t = ((sb[0][f] + sb[1][f]) + sb[2][f]) + sb[3][f];
        part[blockIdx.x * 64 + f] = t;
    }
}
__global__ void k_reduce_mean(const float* __restrict__ part, int nb, int n,
                              float* __restrict__ stats)
{
    int f = threadIdx.x;
    float s = 0.f;
    for (int b = 0; b < nb; b++) s += part[b * 64 + f];
    stats[f] = s / (float)n;
}
__global__ void __launch_bounds__(256) k_sum_var(
    const float* __restrict__ h, int n, const float* __restrict__ stats,
    float* __restrict__ part)
{
    __shared__ float sb[4][64];
    int f = threadIdx.x & 63;
    int ty = threadIdx.x >> 6;
    float mean = stats[f];
    float s = 0.f;
    for (int r = blockIdx.x * 4 + ty; r < n; r += gridDim.x * 4) {
        float d = h[(size_t)r * 64 + f] - mean;
        s = fmaf(d, d, s);
    }
    sb[ty][f] = s;
    __syncthreads();
    if (threadIdx.x < 64) {
        float t = ((sb[0][f] + sb[1][f]) + sb[2][f]) + sb[3][f];
        part[blockIdx.x * 64 + f] = t;
    }
}
__global__ void k_reduce_var(const float* __restrict__ part, int nb, int n,
                             const float* __restrict__ gamma,
                             const float* __restrict__ beta,
                             float* __restrict__ stats)
{
    int f = threadIdx.x;
    float s = 0.f;
    for (int b = 0; b < nb; b++) s += part[b * 64 + f];
    float var = s / (float)n;
    float mean = stats[f];
    float rstd = rsqrtf(var + 1e-5f);
    float sc = rstd * gamma[f];
    stats[128 + f] = sc;
    stats[192 + f] = beta[f] - mean * sc;
}

// =====================================================================
// Final head
// =====================================================================
__global__ void __launch_bounds__(256) k_final(
    const float2* __restrict__ h3, const float* __restrict__ stats,
    const float* __restrict__ W2, const float* __restrict__ b2,
    const float* __restrict__ W3, const float* __restrict__ b3,
    float* __restrict__ out, int n)
{
    __shared__ float W2s[D_HID * N_CLS];
    __shared__ float W3s[N_CLS * N_CLS];
    __shared__ float hb[8][D_HID];
    __shared__ float tb[8][N_CLS];
    int tid = threadIdx.x;
    {
        const float4* s2 = (const float4*)W2;
        float4* d2 = (float4*)W2s;
        d2[tid] = s2[tid];
        d2[tid + 256] = s2[tid + 256];
        ((float4*)W3s)[tid] = ((const float4*)W3)[tid];
    }
    __syncthreads();
    int lane = tid & 31, w = tid >> 5;
    int node = blockIdx.x * 8 + w;
    if (node >= n) return;
    float2 h = h3[node * 32 + lane];
    float s0 = stats[128 + 2 * lane], s1 = stats[128 + 2 * lane + 1];
    float t0 = stats[192 + 2 * lane], t1 = stats[192 + 2 * lane + 1];
    hb[w][2 * lane]     = fmaf(h.x, s0, t0);
    hb[w][2 * lane + 1] = fmaf(h.y, s1, t1);
    __syncwarp();
    float t = b2[lane];
#pragma unroll
    for (int k = 0; k < D_HID; k++) t = fmaf(hb[w][k], W2s[k * 32 + lane], t);
    t = fmaxf(t, 0.f);
    tb[w][lane] = t;
    __syncwarp();
    float o = b3[lane];
#pragma unroll
    for (int k = 0; k < N_CLS; k++) o = fmaf(tb[w][k], W3s[k * 32 + lane], o);
    out[(size_t)node * 32 + lane] = o;
}

// =====================================================================
// launch  (k_lin1_mma kept in the ncu-profiled slot #4)
// =====================================================================
extern "C" void kernel_launch(void* const* d_in, const int* in_sizes, int n_in,
                              void* d_out, int out_size) {
    const float* x     = (const float*)d_in[0];
    const float* W1    = (const float*)d_in[1];
    const float* b1    = (const float*)d_in[2];
    const float* Wc1   = (const float*)d_in[3];
    const float* bc1   = (const float*)d_in[4];
    const float* Wc2   = (const float*)d_in[5];
    const float* bc2   = (const float*)d_in[6];
    const float* Wc3   = (const float*)d_in[7];
    const float* bc3   = (const float*)d_in[8];
    const float* gamma = (const float*)d_in[9];
    const float* beta  = (const float*)d_in[10];
    const float* W2    = (const float*)d_in[11];
    const float* b2    = (const float*)d_in[12];
    const float* W3    = (const float*)d_in[13];
    const float* b3    = (const float*)d_in[14];
    const int*   ei    = (const int*)d_in[15];

    int n = in_sizes[0] / F_IN;
    int E = in_sizes[15] / 2;
    const int* src = ei;
    const int* dst = ei + E;

    float *bufA, *bufB, *stats, *part, *w1th, *w1tl;
    int *deg, *incl, *bsum, *rp, *cur, *colb;
    cudaGetSymbolAddress((void**)&bufA, g_bufA);
    cudaGetSymbolAddress((void**)&bufB, g_bufB);
    cudaGetSymbolAddress((void**)&stats, g_stats);
    cudaGetSymbolAddress((void**)&part, g_part);
    cudaGetSymbolAddress((void**)&w1th, g_W1T_hi);
    cudaGetSymbolAddress((void**)&w1tl, g_W1T_lo);
    cudaGetSymbolAddress((void**)&deg, g_deg);
    cudaGetSymbolAddress((void**)&incl, g_incl);
    cudaGetSymbolAddress((void**)&bsum, g_bsum);
    cudaGetSymbolAddress((void**)&rp, g_rp);
    cudaGetSymbolAddress((void**)&cur, g_cur);
    cudaGetSymbolAddress((void**)&colb, g_col);

    cudaFuncSetAttribute(k_lin1_mma, cudaFuncAttributeMaxDynamicSharedMemorySize, MMA_SMEM);

    int NB = (n + 511) / 512;
    int ablocks = (n + 7) / 8;
    int mblocks = (n + 127) / 128;

    // prepW first; k_lin1_mma in launch slot #4 (ncu capture slot).
    k_prepW<<<64, 256>>>(W1, w1th, w1tl);
    k_zero_int<<<(n + 255) / 256, 256>>>(deg, n);
    k_hist<<<(E + 255) / 256, 256>>>(dst, E, deg);
    k_lin1_mma<<<mblocks, 512, MMA_SMEM>>>(x, w1th, w1tl, b1, Wc1, bufA, n);
    k_scan1<<<NB, 512>>>(deg, n, incl, bsum);
    k_scan1<<<1, 512>>>(bsum, NB, bsum, (int*)0);
    k_scan3<<<(n + 255) / 256, 256>>>(incl, bsum, deg, rp, cur, n);
    k_fill<<<(E + 255) / 256, 256>>>(src, dst, E, cur, colb);
    k_sortseg<<<ablocks, 256>>>(rp, colb, n);

    // conv1 (+Wc2 pre-applied), conv2 (+Wc3 pre-applied), conv3
    k_agg_mm<<<ablocks, 256>>>((const float2*)bufA, (float2*)bufB, rp, colb, bc1, Wc2, n);
    k_agg_mm<<<ablocks, 256>>>((const float2*)bufB, (float2*)bufA, rp, colb, bc2, Wc3, n);
    k_agg_final<<<ablocks, 256>>>((const float2*)bufA, (float2*)bufB, rp, colb, bc3, n);

    // deterministic two-pass batchnorm stats + head
    k_sum_mean<<<256, 256>>>(bufB, n, part);
    k_reduce_mean<<<1, 64>>>(part, 256, n, stats);
    k_sum_var<<<256, 256>>>(bufB, n, stats, part);
    k_reduce_var<<<1, 64>>>(part, 256, n, gamma, beta, stats);
    k_final<<<ablocks, 256>>>((const float2*)bufB, stats, W2, b2, W3, b3,
                              (float*)d_out, n);
}

// round 7
// speedup vs baseline: 1.2445x; 1.0275x over previous
#include <cuda_runtime.h>
#include <cuda_bf16.h>
#include <cstdint>

typedef unsigned long long ull;

#define F_IN   512
#define D_EMB  128
#define D_HID  64
#define N_CLS  32
#define MAXN   100000
#define MAXE   1600000

// ---------------- device scratch (no allocation allowed) ----------------
__device__ float g_bufA[MAXN * D_HID];
__device__ float g_bufB[MAXN * D_HID];
__device__ int   g_deg [MAXN + 2];
__device__ int   g_incl[MAXN + 2];
__device__ int   g_bsum[512];
__device__ int   g_rp  [MAXN + 2];
__device__ int   g_cur [MAXN + 2];
__device__ int   g_col [MAXE + 2];
__device__ float g_stats[256];
__device__ float g_part[256 * 64];
__device__ float g_W1T_hi[D_EMB * F_IN];
__device__ float g_W1T_lo[D_EMB * F_IN];

// ---------------- helpers ----------------
__device__ __forceinline__ ull dup2(float v) {
    ull r; asm("mov.b64 %0, {%1, %1};" : "=l"(r) : "f"(v)); return r;
}
__device__ __forceinline__ void ffma2(ull &acc, ull a, ull b) {
    asm("fma.rn.f32x2 %0, %1, %2, %0;" : "+l"(acc) : "l"(a), "l"(b));
}
__device__ __forceinline__ float2 unpack2(ull v) {
    float2 r; asm("mov.b64 {%0, %1}, %2;" : "=f"(r.x), "=f"(r.y) : "l"(v)); return r;
}
__device__ __forceinline__ float tf32r(float v) {
    uint32_t r; asm("cvt.rna.tf32.f32 %0, %1;" : "=r"(r) : "f"(v));
    return __uint_as_float(r);
}

// portable tensor-core MMA: m16n8k8 tf32, float4 A-frag + float2 B-frag
#define MMA_TF32_V(c, a4, b2)                                                   \
    asm volatile(                                                               \
        "mma.sync.aligned.m16n8k8.row.col.f32.tf32.tf32.f32 "                   \
        "{%0,%1,%2,%3}, {%4,%5,%6,%7}, {%8,%9}, {%0,%1,%2,%3};"                 \
        : "+f"((c)[0]), "+f"((c)[1]), "+f"((c)[2]), "+f"((c)[3])                \
        : "r"(__float_as_uint((a4).x)), "r"(__float_as_uint((a4).y)),           \
          "r"(__float_as_uint((a4).z)), "r"(__float_as_uint((a4).w)),           \
          "r"(__float_as_uint((b2).x)), "r"(__float_as_uint((b2).y)))

// =====================================================================
// k_prepW: W1[512][128] -> W1T_hi/lo[128][512] (transpose + tf32 split)
// =====================================================================
__global__ void __launch_bounds__(256) k_prepW(
    const float* __restrict__ W1, float* __restrict__ hiT, float* __restrict__ loT)
{
    __shared__ float ts[32][33];
    int kt = blockIdx.x & 15, nt = blockIdx.x >> 4;
    int tx = threadIdx.x & 31, ty = threadIdx.x >> 5;   // ty 0..7
#pragma unroll
    for (int r = 0; r < 4; r++) {
        int k = kt * 32 + ty + r * 8;
        ts[ty + r * 8][tx] = W1[k * D_EMB + nt * 32 + tx];
    }
    __syncthreads();
#pragma unroll
    for (int r = 0; r < 4; r++) {
        int nn = nt * 32 + ty + r * 8;
        float v = ts[tx][ty + r * 8];
        float hi = tf32r(v);
        float lo = tf32r(v - hi);
        hiT[nn * F_IN + kt * 32 + tx] = hi;
        loT[nn * F_IN + kt * 32 + tx] = lo;
    }
}

// =====================================================================
// k_lin1_mma: g1 = relu(x @ W1 + b1) @ Wc1 via 3xTF32 mma.sync
// 512 threads; CTA tile 128x128; 16 warps 4x4 grid, warp tile 32x32.
// Fragment-major smem layout, double-buffered stages.
//
// smem (floats):
//   [0 .. 2*17152)    two stages; per stage: A_hi(4224) A_lo(4224)
//                     B_hi(4352) B_lo(4352); blocks padded (132/68)
//                     (stage 0 reused as Hs[128][132] in the epilogue)
//   [34304 .. 42496)  WcS (Wc1, 128x64)
//   [42496 .. 42624)  b1s
// =====================================================================
#define STAGE_F  17152
#define AOFF_HI  0
#define AOFF_LO  4224
#define BOFF_HI  8448
#define BOFF_LO  12800
#define MMA_SMEM ((2 * STAGE_F + 8192 + 128) * 4)
#define LIN1_HSS 132

__global__ void __launch_bounds__(512) k_lin1_mma(
    const float* __restrict__ x, const float* __restrict__ Whi,
    const float* __restrict__ Wlo, const float* __restrict__ b1,
    const float* __restrict__ Wc1, float* __restrict__ g1, int n)
{
    extern __shared__ float sm[];
    float* tiles = sm;
    float* WcS   = sm + 2 * STAGE_F;
    float* b1s   = WcS + 8192;
    float* Hs    = sm;                       // epilogue overlay (stage 0)

    const int tid  = threadIdx.x;
    const int wid  = tid >> 5, lane = tid & 31;
    const int wm   = wid & 3, wn = wid >> 2;       // 4x4 warp grid
    const int row0 = blockIdx.x * 128;

    // load Wc1 + b1 (persist; separate smem region)
    {
        const float4* s = (const float4*)Wc1;
        float4* d = (float4*)WcS;
#pragma unroll
        for (int i = 0; i < 4; i++) d[tid + i * 512] = s[tid + i * 512];
        if (tid < 128) b1s[tid] = b1[tid];
    }

    float c[2][4][4];
#pragma unroll
    for (int am = 0; am < 2; am++)
#pragma unroll
        for (int an = 0; an < 4; an++)
#pragma unroll
            for (int q = 0; q < 4; q++) c[am][an][q] = 0.f;

    // writer indices (per thread, per it)
    //   idx = tid + it*512 ; m/nn = idx>>3 (0..127) ; j4 = idx&7
    //   ks = j4>>1 ; q = j4&1 ; element t (0..3) -> k = ks*8 + q*4 + t
    float4 xa[2], wbh[2], wbl[2];

    auto FETCH = [&](int kc) {
#pragma unroll
        for (int it = 0; it < 2; it++) {
            int idx = tid + it * 512;
            int m = idx >> 3, j4 = idx & 7;
            bool v = (row0 + m) < n;
            xa[it] = v ? *(const float4*)(x + (size_t)(row0 + m) * F_IN + kc * 32 + j4 * 4)
                       : make_float4(0.f, 0.f, 0.f, 0.f);
            wbh[it] = *(const float4*)(Whi + (size_t)m * F_IN + kc * 32 + j4 * 4);
            wbl[it] = *(const float4*)(Wlo + (size_t)m * F_IN + kc * 32 + j4 * 4);
        }
    };
    auto STORE = [&](float* bs) {
#pragma unroll
        for (int it = 0; it < 2; it++) {
            int idx = tid + it * 512;
            int m = idx >> 3, j4 = idx & 7;
            int ks = j4 >> 1, q = j4 & 1;
            // A frag slot = h + 2q ; block = (mt*4+ks), stride 132
            int mt = m >> 4, h = (m >> 3) & 1, gid = m & 7;
            float4 a = xa[it];
            float hx = tf32r(a.x), lx = tf32r(a.x - hx);
            float hy = tf32r(a.y), ly = tf32r(a.y - hy);
            float hz = tf32r(a.z), lz = tf32r(a.z - hz);
            float hw = tf32r(a.w), lw = tf32r(a.w - hw);
            int baseA = (mt * 4 + ks) * 132 + gid * 16 + (h + 2 * q);
            float* ah = bs + AOFF_HI + baseA;
            float* al = bs + AOFF_LO + baseA;
            ah[0] = hx; ah[4] = hy; ah[8] = hz; ah[12] = hw;
            al[0] = lx; al[4] = ly; al[8] = lz; al[12] = lw;
            // B frag slot = q ; block = (ntile*4+ks), stride 68
            int ntile = m >> 3, gidB = m & 7;
            int baseB = (ntile * 4 + ks) * 68 + gidB * 8 + q;
            float* bh = bs + BOFF_HI + baseB;
            float* bl = bs + BOFF_LO + baseB;
            float4 h4 = wbh[it], l4 = wbl[it];
            bh[0] = h4.x; bh[2] = h4.y; bh[4] = h4.z; bh[6] = h4.w;
            bl[0] = l4.x; bl[2] = l4.y; bl[4] = l4.z; bl[6] = l4.w;
        }
    };

    FETCH(0);
    STORE(tiles);
    __syncthreads();

    for (int kc = 0; kc < 16; kc++) {
        if (kc + 1 < 16) FETCH(kc + 1);
        const float* st = tiles + (kc & 1) * STAGE_F;
#pragma unroll
        for (int ks = 0; ks < 4; ks++) {
            float4 ahf[2], alf[2];
#pragma unroll
            for (int am = 0; am < 2; am++) {
                int bA = ((wm * 2 + am) * 4 + ks) * 132 + lane * 4;
                ahf[am] = *(const float4*)(st + AOFF_HI + bA);
                alf[am] = *(const float4*)(st + AOFF_LO + bA);
            }
#pragma unroll
            for (int an = 0; an < 4; an++) {
                int bB = ((wn * 4 + an) * 4 + ks) * 68 + lane * 2;
                float2 bhf = *(const float2*)(st + BOFF_HI + bB);
                float2 blf = *(const float2*)(st + BOFF_LO + bB);
#pragma unroll
                for (int am = 0; am < 2; am++) {
                    MMA_TF32_V(c[am][an], ahf[am], bhf);
                    MMA_TF32_V(c[am][an], ahf[am], blf);
                    MMA_TF32_V(c[am][an], alf[am], bhf);
                }
            }
        }
        if (kc + 1 < 16) STORE(tiles + ((kc + 1) & 1) * STAGE_F);
        __syncthreads();
    }
    __syncthreads();   // all warps done with stage-1 reads before Hs overlay

    // ---- epilogue 1: bias + relu, stage into Hs[128][132] ----
    const int gid = lane >> 2, tig = lane & 3;
#pragma unroll
    for (int am = 0; am < 2; am++) {
        int r0 = wm * 32 + am * 16 + gid;
#pragma unroll
        for (int an = 0; an < 4; an++) {
            int col = wn * 32 + an * 8 + 2 * tig;
            float bb0 = b1s[col], bb1 = b1s[col + 1];
            float2 lo2 = make_float2(fmaxf(c[am][an][0] + bb0, 0.f),
                                     fmaxf(c[am][an][1] + bb1, 0.f));
            float2 hi2 = make_float2(fmaxf(c[am][an][2] + bb0, 0.f),
                                     fmaxf(c[am][an][3] + bb1, 0.f));
            *(float2*)(Hs + r0 * LIN1_HSS + col)       = lo2;
            *(float2*)(Hs + (r0 + 8) * LIN1_HSS + col) = hi2;
        }
    }
    __syncthreads();

    // ---- epilogue 2: g1[128][64] = Hs[128][128] @ WcS[128][64] ----
    {
        int tx = tid & 15, ty = tid >> 4;
        ull o[4][2];
#pragma unroll
        for (int r = 0; r < 4; r++) { o[r][0] = 0ull; o[r][1] = 0ull; }
#pragma unroll 8
        for (int em = 0; em < D_EMB; em++) {
            double2 wp = *(const double2*)(WcS + em * D_HID + tx * 4);
            ull w0 = __double_as_longlong(wp.x);
            ull w1 = __double_as_longlong(wp.y);
#pragma unroll
            for (int r = 0; r < 4; r++) {
                ull hd = dup2(Hs[(ty * 4 + r) * LIN1_HSS + em]);
                ffma2(o[r][0], hd, w0);
                ffma2(o[r][1], hd, w1);
            }
        }
#pragma unroll
        for (int r = 0; r < 4; r++) {
            int m = ty * 4 + r;
            if (row0 + m < n) {
                float2 e = unpack2(o[r][0]), f = unpack2(o[r][1]);
                *(float4*)(g1 + (size_t)(row0 + m) * D_HID + tx * 4) =
                    make_float4(e.x, e.y, f.x, f.y);
            }
        }
    }
}

// =====================================================================
// CSR build
// =====================================================================
__global__ void k_zero_int(int* p, int n) {
    int i = blockIdx.x * blockDim.x + threadIdx.x;
    if (i < n) p[i] = 0;
}
__global__ void k_hist(const int* __restrict__ dst, int E, int* __restrict__ deg) {
    int e = blockIdx.x * blockDim.x + threadIdx.x;
    if (e < E) atomicAdd(&deg[dst[e]], 1);
}
__global__ void k_scan1(const int* __restrict__ in, int n,
                        int* __restrict__ incl, int* __restrict__ bsum) {
    __shared__ int s[512];
    int i = blockIdx.x * 512 + threadIdx.x;
    s[threadIdx.x] = (i < n) ? in[i] : 0;
    __syncthreads();
#pragma unroll
    for (int off = 1; off < 512; off <<= 1) {
        int t = (threadIdx.x >= off) ? s[threadIdx.x - off] : 0;
        __syncthreads();
        s[threadIdx.x] += t;
        __syncthreads();
    }
    if (i < n) incl[i] = s[threadIdx.x];
    if (bsum && threadIdx.x == 511) bsum[blockIdx.x] = s[511];
}
__global__ void k_scan3(const int* __restrict__ incl, const int* __restrict__ bsum,
                        const int* __restrict__ deg, int* __restrict__ rp,
                        int* __restrict__ cur, int n) {
    int i = blockIdx.x * blockDim.x + threadIdx.x;
    if (i >= n) return;
    int b = i >> 9;
    int off = (b > 0) ? bsum[b - 1] : 0;
    int v = incl[i] + off;
    rp[i + 1] = v;
    cur[i] = v - deg[i];
    if (i == 0) rp[0] = 0;
}
__global__ void k_fill(const int* __restrict__ src, const int* __restrict__ dst,
                       int E, int* __restrict__ cur, int* __restrict__ col) {
    int e = blockIdx.x * blockDim.x + threadIdx.x;
    if (e >= E) return;
    int pos = atomicAdd(&cur[dst[e]], 1);
    col[pos] = src[e];
}

// =====================================================================
// Canonicalize CSR segment order (determinism)
// =====================================================================
__global__ void __launch_bounds__(256) k_sortseg(
    const int* __restrict__ rp, int* __restrict__ col, int n)
{
    __shared__ int sbuf[8][1024];
    int lane = threadIdx.x & 31, w = threadIdx.x >> 5;
    int node = blockIdx.x * 8 + w;
    if (node >= n) return;
    int beg = rp[node], end = rp[node + 1];
    int d = end - beg;
    if (d <= 1) return;

    if (d <= 32) {
        int v = (lane < d) ? col[beg + lane] : 0x7fffffff;
#pragma unroll
        for (int k = 2; k <= 32; k <<= 1) {
#pragma unroll
            for (int j = k >> 1; j > 0; j >>= 1) {
                int other = __shfl_xor_sync(0xffffffffu, v, j);
                bool dirUp = ((lane & k) == 0);
                bool takeMin = (((lane & j) == 0) == dirUp);
                v = takeMin ? min(v, other) : max(v, other);
            }
        }
        if (lane < d) col[beg + lane] = v;
    } else if (d <= 1024) {
        int* s = sbuf[w];
        for (int i = lane; i < d; i += 32) s[i] = col[beg + i];
        __syncwarp();
        for (int ph = 0; ph < d; ph++) {
            int start = ph & 1;
            for (int i = start + 2 * lane; i + 1 < d; i += 64) {
                int a = s[i], b = s[i + 1];
                if (a > b) { s[i] = b; s[i + 1] = a; }
            }
            __syncwarp();
        }
        for (int i = lane; i < d; i += 32) col[beg + i] = s[i];
    } else {
        if (lane == 0) {
            for (int i = beg + 1; i < end; i++) {
                int key = col[i];
                int j = i - 1;
                while (j >= beg && col[j] > key) { col[j + 1] = col[j]; j--; }
                col[j + 1] = key;
            }
        }
    }
}

// =====================================================================
// Aggregation: warp per node, MLP=8 gather.
// =====================================================================
__device__ __forceinline__ void warp_agg(const float2* __restrict__ gin,
                                         const int* __restrict__ col,
                                         int beg, int end, int lane,
                                         float& ax, float& ay) {
    ax = 0.f; ay = 0.f;
    for (int e0 = beg; e0 < end; e0 += 32) {
        int idx = e0 + lane;
        int c = (idx < end) ? __ldg(&col[idx]) : 0;
        int cnt = min(32, end - e0);
        int j = 0;
        for (; j + 8 <= cnt; j += 8) {
            int s0 = __shfl_sync(0xffffffffu, c, j);
            int s1 = __shfl_sync(0xffffffffu, c, j + 1);
            int s2 = __shfl_sync(0xffffffffu, c, j + 2);
            int s3 = __shfl_sync(0xffffffffu, c, j + 3);
            int s4 = __shfl_sync(0xffffffffu, c, j + 4);
            int s5 = __shfl_sync(0xffffffffu, c, j + 5);
            int s6 = __shfl_sync(0xffffffffu, c, j + 6);
            int s7 = __shfl_sync(0xffffffffu, c, j + 7);
            float2 v0 = gin[s0 * 32 + lane];
            float2 v1 = gin[s1 * 32 + lane];
            float2 v2 = gin[s2 * 32 + lane];
            float2 v3 = gin[s3 * 32 + lane];
            float2 v4 = gin[s4 * 32 + lane];
            float2 v5 = gin[s5 * 32 + lane];
            float2 v6 = gin[s6 * 32 + lane];
            float2 v7 = gin[s7 * 32 + lane];
            ax += v0.x; ay += v0.y;
            ax += v1.x; ay += v1.y;
            ax += v2.x; ay += v2.y;
            ax += v3.x; ay += v3.y;
            ax += v4.x; ay += v4.y;
            ax += v5.x; ay += v5.y;
            ax += v6.x; ay += v6.y;
            ax += v7.x; ay += v7.y;
        }
        for (; j < cnt; j++) {
            int s = __shfl_sync(0xffffffffu, c, j);
            float2 v = gin[s * 32 + lane];
            ax += v.x; ay += v.y;
        }
    }
}

#define HT_STRIDE 10
__global__ void __launch_bounds__(256) k_agg_mm(
    const float2* __restrict__ gin, float2* __restrict__ gout,
    const int* __restrict__ rp, const int* __restrict__ col,
    const float* __restrict__ bias, const float* __restrict__ W, int n)
{
    __shared__ float Ws[D_HID * D_HID];
    __shared__ float hT[D_HID][HT_STRIDE];
    int tid = threadIdx.x;
    {
        const float4* s = (const float4*)W;
        float4* d = (float4*)Ws;
#pragma unroll
        for (int i = 0; i < 4; i++) d[tid + i * 256] = s[tid + i * 256];
    }
    int lane = tid & 31, w = tid >> 5;
    int node = blockIdx.x * 8 + w;
    if (node < n) {
        int beg = rp[node], end = rp[node + 1];
        float ax, ay;
        warp_agg(gin, col, beg, end, lane, ax, ay);
        float inv = 1.f / fmaxf((float)(end - beg), 1.f);
        float b0 = bias[2 * lane], b1v = bias[2 * lane + 1];
        hT[2 * lane][w]     = fmaxf(fmaf(ax, inv, b0), 0.f);
        hT[2 * lane + 1][w] = fmaxf(fmaf(ay, inv, b1v), 0.f);
    }
    __syncthreads();
    if (w < 4) {
        int n0 = blockIdx.x * 8 + 2 * w;
        if (n0 < n) {
            int n1 = n0 + 1;
            const float2* wsp = (const float2*)Ws;
            ull oXe = 0ull, oXo = 0ull, oYe = 0ull, oYo = 0ull;
#pragma unroll
            for (int k = 0; k < D_HID; k += 2) {
                ull h0 = *(const ull*)(&hT[k][2 * w]);
                ull h1 = *(const ull*)(&hT[k + 1][2 * w]);
                float2 w0 = wsp[k * 32 + lane];
                float2 w1 = wsp[(k + 1) * 32 + lane];
                ffma2(oXe, h0, dup2(w0.x));
                ffma2(oYe, h0, dup2(w0.y));
                ffma2(oXo, h1, dup2(w1.x));
                ffma2(oYo, h1, dup2(w1.y));
            }
            float2 xe = unpack2(oXe), xo = unpack2(oXo);
            float2 ye = unpack2(oYe), yo = unpack2(oYo);
            gout[n0 * 32 + lane] = make_float2(xe.x + xo.x, ye.x + yo.x);
            if (n1 < n)
                gout[n1 * 32 + lane] = make_float2(xe.y + xo.y, ye.y + yo.y);
        }
    }
}

__global__ void __launch_bounds__(256) k_agg_final(
    const float2* __restrict__ gin, float2* __restrict__ gout,
    const int* __restrict__ rp, const int* __restrict__ col,
    const float* __restrict__ bias, int n)
{
    int tid = threadIdx.x;
    int lane = tid & 31, w = tid >> 5;
    int node = blockIdx.x * 8 + w;
    if (node >= n) return;
    int beg = rp[node], end = rp[node + 1];
    float ax, ay;
    warp_agg(gin, col, beg, end, lane, ax, ay);
    float inv = 1.f / fmaxf((float)(end - beg), 1.f);
    float b0 = bias[2 * lane], b1v = bias[2 * lane + 1];
    float2 h;
    h.x = fmaxf(fmaf(ax, inv, b0), 0.f);
    h.y = fmaxf(fmaf(ay, inv, b1v), 0.f);
    gout[node * 32 + lane] = h;
}

// =====================================================================
// Deterministic two-pass batchnorm statistics
// =====================================================================
__global__ void __launch_bounds__(256) k_sum_mean(
    const float* __restrict__ h, int n, float* __restrict__ part)
{
    __shared__ float sb[4][64];
    int f = threadIdx.x & 63;
    int ty = threadIdx.x >> 6;
    float s = 0.f;
    for (int r = blockIdx.x * 4 + ty; r < n; r += gridDim.x * 4)
        s += h[(size_t)r * 64 + f];
    sb[ty][f] = s;
    __syncthreads();
    if (threadIdx.x < 64) {
        float t = ((sb[0][f] + sb[1][f]) + sb[2][f]) + sb[3][f];
        part[blockIdx.x * 64 + f] = t;
    }
}
__global__ void k_reduce_mean(const float* __restrict__ part, int nb, int n,
                              float* __restrict__ stats)
{
    int f = threadIdx.x;
    float s = 0.f;
    for (int b = 0; b < nb; b++) s += part[b * 64 + f];
    stats[f] = s / (float)n;
}
__global__ void __launch_bounds__(256) k_sum_var(
    const float* __restrict__ h, int n, const float* __restrict__ stats,
    float* __restrict__ part)
{
    __shared__ float sb[4][64];
    int f = threadIdx.x & 63;
    int ty = threadIdx.x >> 6;
    float mean = stats[f];
    float s = 0.f;
    for (int r = blockIdx.x * 4 + ty; r < n; r += gridDim.x * 4) {
        float d = h[(size_t)r * 64 + f] - mean;
        s = fmaf(d, d, s);
    }
    sb[ty][f] = s;
    __syncthreads();
    if (threadIdx.x < 64) {
        float t = ((sb[0][f] + sb[1][f]) + sb[2][f]) + sb[3][f];
        part[blockIdx.x * 64 + f] = t;
    }
}
__global__ void k_reduce_var(const float* __restrict__ part, int nb, int n,
                             const float* __restrict__ gamma,
                             const float* __restrict__ beta,
                             float* __restrict__ stats)
{
    int f = threadIdx.x;
    float s = 0.f;
    for (int b = 0; b < nb; b++) s += part[b * 64 + f];
    float var = s / (float)n;
    float mean = stats[f];
    float rstd = rsqrtf(var + 1e-5f);
    float sc = rstd * gamma[f];
    stats[128 + f] = sc;
    stats[192 + f] = beta[f] - mean * sc;
}

// =====================================================================
// Final head
// =====================================================================
__global__ void __launch_bounds__(256) k_final(
    const float2* __restrict__ h3, const float* __restrict__ stats,
    const float* __restrict__ W2, const float* __restrict__ b2,
    const float* __restrict__ W3, const float* __restrict__ b3,
    float* __restrict__ out, int n)
{
    __shared__ float W2s[D_HID * N_CLS];
    __shared__ float W3s[N_CLS * N_CLS];
    __shared__ float hb[8][D_HID];
    __shared__ float tb[8][N_CLS];
    int tid = threadIdx.x;
    {
        const float4* s2 = (const float4*)W2;
        float4* d2 = (float4*)W2s;
        d2[tid] = s2[tid];
        d2[tid + 256] = s2[tid + 256];
        ((float4*)W3s)[tid] = ((const float4*)W3)[tid];
    }
    __syncthreads();
    int lane = tid & 31, w = tid >> 5;
    int node = blockIdx.x * 8 + w;
    if (node >= n) return;
    float2 h = h3[node * 32 + lane];
    float s0 = stats[128 + 2 * lane], s1 = stats[128 + 2 * lane + 1];
    float t0 = stats[192 + 2 * lane], t1 = stats[192 + 2 * lane + 1];
    hb[w][2 * lane]     = fmaf(h.x, s0, t0);
    hb[w][2 * lane + 1] = fmaf(h.y, s1, t1);
    __syncwarp();
    float t = b2[lane];
#pragma unroll
    for (int k = 0; k < D_HID; k++) t = fmaf(hb[w][k], W2s[k * 32 + lane], t);
    t = fmaxf(t, 0.f);
    tb[w][lane] = t;
    __syncwarp();
    float o = b3[lane];
#pragma unroll
    for (int k = 0; k < N_CLS; k++) o = fmaf(tb[w][k], W3s[k * 32 + lane], o);
    out[(size_t)node * 32 + lane] = o;
}

// =====================================================================
// launch  (k_lin1_mma kept in the ncu-profiled slot #4)
// =====================================================================
extern "C" void kernel_launch(void* const* d_in, const int* in_sizes, int n_in,
                              void* d_out, int out_size) {
    const float* x     = (const float*)d_in[0];
    const float* W1    = (const float*)d_in[1];
    const float* b1    = (const float*)d_in[2];
    const float* Wc1   = (const float*)d_in[3];
    const float* bc1   = (const float*)d_in[4];
    const float* Wc2   = (const float*)d_in[5];
    const float* bc2   = (const float*)d_in[6];
    const float* Wc3   = (const float*)d_in[7];
    const float* bc3   = (const float*)d_in[8];
    const float* gamma = (const float*)d_in[9];
    const float* beta  = (const float*)d_in[10];
    const float* W2    = (const float*)d_in[11];
    const float* b2    = (const float*)d_in[12];
    const float* W3    = (const float*)d_in[13];
    const float* b3    = (const float*)d_in[14];
    const int*   ei    = (const int*)d_in[15];

    int n = in_sizes[0] / F_IN;
    int E = in_sizes[15] / 2;
    const int* src = ei;
    const int* dst = ei + E;

    float *bufA, *bufB, *stats, *part, *w1th, *w1tl;
    int *deg, *incl, *bsum, *rp, *cur, *colb;
    cudaGetSymbolAddress((void**)&bufA, g_bufA);
    cudaGetSymbolAddress((void**)&bufB, g_bufB);
    cudaGetSymbolAddress((void**)&stats, g_stats);
    cudaGetSymbolAddress((void**)&part, g_part);
    cudaGetSymbolAddress((void**)&w1th, g_W1T_hi);
    cudaGetSymbolAddress((void**)&w1tl, g_W1T_lo);
    cudaGetSymbolAddress((void**)&deg, g_deg);
    cudaGetSymbolAddress((void**)&incl, g_incl);
    cudaGetSymbolAddress((void**)&bsum, g_bsum);
    cudaGetSymbolAddress((void**)&rp, g_rp);
    cudaGetSymbolAddress((void**)&cur, g_cur);
    cudaGetSymbolAddress((void**)&colb, g_col);

    cudaFuncSetAttribute(k_lin1_mma, cudaFuncAttributeMaxDynamicSharedMemorySize, MMA_SMEM);

    int NB = (n + 511) / 512;
    int ablocks = (n + 7) / 8;
    int mblocks = (n + 127) / 128;

    // prepW first; k_lin1_mma in launch slot #4 (ncu capture slot).
    k_prepW<<<64, 256>>>(W1, w1th, w1tl);
    k_zero_int<<<(n + 255) / 256, 256>>>(deg, n);
    k_hist<<<(E + 255) / 256, 256>>>(dst, E, deg);
    k_lin1_mma<<<mblocks, 512, MMA_SMEM>>>(x, w1th, w1tl, b1, Wc1, bufA, n);
    k_scan1<<<NB, 512>>>(deg, n, incl, bsum);
    k_scan1<<<1, 512>>>(bsum, NB, bsum, (int*)0);
    k_scan3<<<(n + 255) / 256, 256>>>(incl, bsum, deg, rp, cur, n);
    k_fill<<<(E + 255) / 256, 256>>>(src, dst, E, cur, colb);
    k_sortseg<<<ablocks, 256>>>(rp, colb, n);

    // conv1 (+Wc2 pre-applied), conv2 (+Wc3 pre-applied), conv3
    k_agg_mm<<<ablocks, 256>>>((const float2*)bufA, (float2*)bufB, rp, colb, bc1, Wc2, n);
    k_agg_mm<<<ablocks, 256>>>((const float2*)bufB, (float2*)bufA, rp, colb, bc2, Wc3, n);
    k_agg_final<<<ablocks, 256>>>((const float2*)bufA, (float2*)bufB, rp, colb, bc3, n);

    // deterministic two-pass batchnorm stats + head
    k_sum_mean<<<256, 256>>>(bufB, n, part);
    k_reduce_mean<<<1, 64>>>(part, 256, n, stats);
    k_sum_var<<<256, 256>>>(bufB, n, stats, part);
    k_reduce_var<<<1, 64>>>(part, 256, n, gamma, beta, stats);
    k_final<<<ablocks, 256>>>((const float2*)bufB, stats, W2, b2, W3, b3,
                              (float*)d_out, n);
}

// round 8
// speedup vs baseline: 1.4599x; 1.1731x over previous
#include <cuda_runtime.h>
#include <cuda_bf16.h>
#include <cstdint>

typedef unsigned long long ull;

#define F_IN   512
#define D_EMB  128
#define D_HID  64
#define N_CLS  32
#define MAXN   100000
#define MAXE   1600000

// ---------------- device scratch (no allocation allowed) ----------------
__device__ float g_bufA[MAXN * D_HID];
__device__ float g_bufB[MAXN * D_HID];
__device__ int   g_deg [MAXN + 2];
__device__ int   g_incl[MAXN + 2];
__device__ int   g_bsum[512];
__device__ int   g_rp  [MAXN + 2];
__device__ int   g_cur [MAXN + 2];
__device__ int   g_col [MAXE + 2];
__device__ float g_stats[256];
__device__ float g_part[256 * 64];
__device__ uint32_t g_Wp_hi[D_EMB * F_IN / 2];
__device__ uint32_t g_Wp_lo[D_EMB * F_IN / 2];

// ---------------- helpers ----------------
__device__ __forceinline__ ull dup2(float v) {
    ull r; asm("mov.b64 %0, {%1, %1};" : "=l"(r) : "f"(v)); return r;
}
__device__ __forceinline__ void ffma2(ull &acc, ull a, ull b) {
    asm("fma.rn.f32x2 %0, %1, %2, %0;" : "+l"(acc) : "l"(a), "l"(b));
}
__device__ __forceinline__ float2 unpack2(ull v) {
    float2 r; asm("mov.b64 {%0, %1}, %2;" : "=f"(r.x), "=f"(r.y) : "l"(v)); return r;
}
// pack two floats (k-even, k-odd) into bf16x2: a -> low half, b -> high half
__device__ __forceinline__ uint32_t pkbf(float a, float b) {
    uint32_t r; asm("cvt.rn.bf16x2.f32 %0, %1, %2;" : "=r"(r) : "f"(b), "f"(a));
    return r;
}
__device__ __forceinline__ float bf16f(float v) {
    return __bfloat162float(__float2bfloat16(v));
}

// portable tensor-core MMA: m16n8k16 bf16 (sm_80+; valid on compute_103)
#define MMA_BF16(c, a, b)                                                       \
    asm volatile(                                                               \
        "mma.sync.aligned.m16n8k16.row.col.f32.bf16.bf16.f32 "                  \
        "{%0,%1,%2,%3}, {%4,%5,%6,%7}, {%8,%9}, {%0,%1,%2,%3};"                 \
        : "+f"((c)[0]), "+f"((c)[1]), "+f"((c)[2]), "+f"((c)[3])                \
        : "r"((a).x), "r"((a).y), "r"((a).z), "r"((a).w),                       \
          "r"((b).x), "r"((b).y))

// =====================================================================
// k_prepW: W1[512][128] -> packed bf16x2 hi/lo, W1T layout [128][256 pairs]
// =====================================================================
__global__ void __launch_bounds__(256) k_prepW(
    const float* __restrict__ W1, uint32_t* __restrict__ hiP,
    uint32_t* __restrict__ loP)
{
    __shared__ float ts[32][33];
    int kt = blockIdx.x & 15, nt = blockIdx.x >> 4;
    int tx = threadIdx.x & 31, ty = threadIdx.x >> 5;   // ty 0..7
#pragma unroll
    for (int r = 0; r < 4; r++) {
        int k = kt * 32 + ty + r * 8;
        ts[ty + r * 8][tx] = W1[k * D_EMB + nt * 32 + tx];
    }
    __syncthreads();
#pragma unroll
    for (int it = 0; it < 2; it++) {
        int idx = threadIdx.x + it * 256;   // 0..511
        int nl = idx >> 4;                  // 0..31
        int q  = idx & 15;                  // pair 0..15
        float v0 = ts[2 * q][nl], v1 = ts[2 * q + 1][nl];
        uint32_t uh = pkbf(v0, v1);
        float h0 = bf16f(v0), h1 = bf16f(v1);
        uint32_t ul = pkbf(v0 - h0, v1 - h1);
        int nn = nt * 32 + nl;
        hiP[nn * 256 + kt * 16 + q] = uh;
        loP[nn * 256 + kt * 16 + q] = ul;
    }
}

// =====================================================================
// k_lin1_mma: g1 = relu(x @ W1 + b1) @ Wc1 via 3x BF16 mma.sync m16n8k16
// 512 threads; CTA tile 128x128; 16 warps 4x4 grid, warp tile 32x32.
// Fragment-major packed-bf16 smem layout, double-buffered stages.
//
// per stage (uints): AH 16 blk x 132 | AL | BH 32 blk x 68 | BL = 8576
// smem (floats): [0 .. 17152) two stages (Hs overlay in epilogue)
//                [17152 .. 25344) WcS ; [25344 .. 25472) b1s
// =====================================================================
#define ABLK 132
#define BBLK 68
#define AH_U 0
#define AL_U (16 * ABLK)
#define BH_U (2 * 16 * ABLK)
#define BL_U (2 * 16 * ABLK + 32 * BBLK)
#define ST_U (2 * 16 * ABLK + 2 * 32 * BBLK)   // 8576
#define MMA_SMEM ((2 * ST_U + 8192 + 128) * 4)
#define LIN1_HSS 132

__global__ void __launch_bounds__(512) k_lin1_mma(
    const float* __restrict__ x, const uint32_t* __restrict__ Whi,
    const uint32_t* __restrict__ Wlo, const float* __restrict__ b1,
    const float* __restrict__ Wc1, float* __restrict__ g1, int n)
{
    extern __shared__ float sm[];
    uint32_t* TL = (uint32_t*)sm;
    float* WcS   = sm + 2 * ST_U;
    float* b1s   = WcS + 8192;
    float* Hs    = sm;                       // epilogue overlay

    const int tid  = threadIdx.x;
    const int wid  = tid >> 5, lane = tid & 31;
    const int wm   = wid & 3, wn = wid >> 2;       // 4x4 warp grid
    const int row0 = blockIdx.x * 128;

    // load Wc1 + b1 (persist; separate smem region)
    {
        const float4* s = (const float4*)Wc1;
        float4* d = (float4*)WcS;
#pragma unroll
        for (int i = 0; i < 4; i++) d[tid + i * 512] = s[tid + i * 512];
        if (tid < 128) b1s[tid] = b1[tid];
    }

    float c[2][4][4];
#pragma unroll
    for (int am = 0; am < 2; am++)
#pragma unroll
        for (int an = 0; an < 4; an++)
#pragma unroll
            for (int q = 0; q < 4; q++) c[am][an][q] = 0.f;

    float4 xa[2];
    uint2  wh[2], wl[2];

    auto FETCH = [&](int kc) {
#pragma unroll
        for (int it = 0; it < 2; it++) {
            int idx = tid + it * 512;
            int m = idx >> 3, j4 = idx & 7;
            bool v = (row0 + m) < n;
            xa[it] = v ? *(const float4*)(x + (size_t)(row0 + m) * F_IN + kc * 32 + j4 * 4)
                       : make_float4(0.f, 0.f, 0.f, 0.f);
            wh[it] = *(const uint2*)(Whi + (size_t)m * 256 + kc * 16 + 2 * j4);
            wl[it] = *(const uint2*)(Wlo + (size_t)m * 256 + kc * 16 + 2 * j4);
        }
    };
    auto STORE = [&](uint32_t* bs) {
#pragma unroll
        for (int it = 0; it < 2; it++) {
            int idx = tid + it * 512;
            int m = idx >> 3, j4 = idx & 7;
            int ks = j4 >> 2, jj = j4 & 3;
            int tig0 = (jj & 1) * 2, ph = jj >> 1;
            // A: split + pack
            float4 a = xa[it];
            uint32_t uh0 = pkbf(a.x, a.y), uh1 = pkbf(a.z, a.w);
            float h0 = bf16f(a.x), h1 = bf16f(a.y);
            float h2 = bf16f(a.z), h3 = bf16f(a.w);
            uint32_t ul0 = pkbf(a.x - h0, a.y - h1);
            uint32_t ul1 = pkbf(a.z - h2, a.w - h3);
            int gid = m & 7, rh = (m >> 3) & 1, mt = m >> 4;
            int s0 = ((mt * 2 + ks)) * ABLK + 16 * gid + 4 * tig0 + rh + 2 * ph;
            bs[AH_U + s0]     = uh0;
            bs[AH_U + s0 + 4] = uh1;
            bs[AL_U + s0]     = ul0;
            bs[AL_U + s0 + 4] = ul1;
            // B: copy packed pairs
            int t0 = ((m >> 3) * 2 + ks) * BBLK + 8 * (m & 7) + 2 * tig0 + ph;
            bs[BH_U + t0]     = wh[it].x;
            bs[BH_U + t0 + 2] = wh[it].y;
            bs[BL_U + t0]     = wl[it].x;
            bs[BL_U + t0 + 2] = wl[it].y;
        }
    };

    FETCH(0);
    STORE(TL);
    __syncthreads();

    for (int kc = 0; kc < 16; kc++) {
        if (kc + 1 < 16) FETCH(kc + 1);
        const uint32_t* st = TL + (kc & 1) * ST_U;
#pragma unroll
        for (int ks = 0; ks < 2; ks++) {
            uint4 ahf[2], alf[2];
#pragma unroll
            for (int am = 0; am < 2; am++) {
                int bA = ((wm * 2 + am) * 2 + ks) * ABLK + lane * 4;
                ahf[am] = *(const uint4*)(st + AH_U + bA);
                alf[am] = *(const uint4*)(st + AL_U + bA);
            }
#pragma unroll
            for (int an = 0; an < 4; an++) {
                int bB = ((wn * 4 + an) * 2 + ks) * BBLK + lane * 2;
                uint2 bhf = *(const uint2*)(st + BH_U + bB);
                uint2 blf = *(const uint2*)(st + BL_U + bB);
#pragma unroll
                for (int am = 0; am < 2; am++) {
                    MMA_BF16(c[am][an], ahf[am], bhf);
                    MMA_BF16(c[am][an], ahf[am], blf);
                    MMA_BF16(c[am][an], alf[am], bhf);
                }
            }
        }
        if (kc + 1 < 16) STORE(TL + ((kc + 1) & 1) * ST_U);
        __syncthreads();
    }
    __syncthreads();   // all warps done with tile reads before Hs overlay

    // ---- epilogue 1: bias + relu, stage into Hs[128][132] ----
    const int gid = lane >> 2, tig = lane & 3;
#pragma unroll
    for (int am = 0; am < 2; am++) {
        int r0 = wm * 32 + am * 16 + gid;
#pragma unroll
        for (int an = 0; an < 4; an++) {
            int col = wn * 32 + an * 8 + 2 * tig;
            float bb0 = b1s[col], bb1 = b1s[col + 1];
            float2 lo2 = make_float2(fmaxf(c[am][an][0] + bb0, 0.f),
                                     fmaxf(c[am][an][1] + bb1, 0.f));
            float2 hi2 = make_float2(fmaxf(c[am][an][2] + bb0, 0.f),
                                     fmaxf(c[am][an][3] + bb1, 0.f));
            *(float2*)(Hs + r0 * LIN1_HSS + col)       = lo2;
            *(float2*)(Hs + (r0 + 8) * LIN1_HSS + col) = hi2;
        }
    }
    __syncthreads();

    // ---- epilogue 2: g1[128][64] = Hs[128][128] @ WcS[128][64] ----
    {
        int tx = tid & 15, ty = tid >> 4;
        ull o[4][2];
#pragma unroll
        for (int r = 0; r < 4; r++) { o[r][0] = 0ull; o[r][1] = 0ull; }
#pragma unroll 8
        for (int em = 0; em < D_EMB; em++) {
            double2 wp = *(const double2*)(WcS + em * D_HID + tx * 4);
            ull w0 = __double_as_longlong(wp.x);
            ull w1 = __double_as_longlong(wp.y);
#pragma unroll
            for (int r = 0; r < 4; r++) {
                ull hd = dup2(Hs[(ty * 4 + r) * LIN1_HSS + em]);
                ffma2(o[r][0], hd, w0);
                ffma2(o[r][1], hd, w1);
            }
        }
#pragma unroll
        for (int r = 0; r < 4; r++) {
            int m = ty * 4 + r;
            if (row0 + m < n) {
                float2 e = unpack2(o[r][0]), f = unpack2(o[r][1]);
                *(float4*)(g1 + (size_t)(row0 + m) * D_HID + tx * 4) =
                    make_float4(e.x, e.y, f.x, f.y);
            }
        }
    }
}

// =====================================================================
// CSR build
// =====================================================================
__global__ void k_zero_int(int* p, int n) {
    int i = blockIdx.x * blockDim.x + threadIdx.x;
    if (i < n) p[i] = 0;
}
__global__ void k_hist(const int* __restrict__ dst, int E, int* __restrict__ deg) {
    int e = blockIdx.x * blockDim.x + threadIdx.x;
    if (e < E) atomicAdd(&deg[dst[e]], 1);
}
__global__ void k_scan1(const int* __restrict__ in, int n,
                        int* __restrict__ incl, int* __restrict__ bsum) {
    __shared__ int s[512];
    int i = blockIdx.x * 512 + threadIdx.x;
    s[threadIdx.x] = (i < n) ? in[i] : 0;
    __syncthreads();
#pragma unroll
    for (int off = 1; off < 512; off <<= 1) {
        int t = (threadIdx.x >= off) ? s[threadIdx.x - off] : 0;
        __syncthreads();
        s[threadIdx.x] += t;
        __syncthreads();
    }
    if (i < n) incl[i] = s[threadIdx.x];
    if (bsum && threadIdx.x == 511) bsum[blockIdx.x] = s[511];
}
__global__ void k_scan3(const int* __restrict__ incl, const int* __restrict__ bsum,
                        const int* __restrict__ deg, int* __restrict__ rp,
                        int* __restrict__ cur, int n) {
    int i = blockIdx.x * blockDim.x + threadIdx.x;
    if (i >= n) return;
    int b = i >> 9;
    int off = (b > 0) ? bsum[b - 1] : 0;
    int v = incl[i] + off;
    rp[i + 1] = v;
    cur[i] = v - deg[i];
    if (i == 0) rp[0] = 0;
}
__global__ void k_fill(const int* __restrict__ src, const int* __restrict__ dst,
                       int E, int* __restrict__ cur, int* __restrict__ col) {
    int e = blockIdx.x * blockDim.x + threadIdx.x;
    if (e >= E) return;
    int pos = atomicAdd(&cur[dst[e]], 1);
    col[pos] = src[e];
}

// =====================================================================
// Canonicalize CSR segment order (determinism)
// =====================================================================
__global__ void __launch_bounds__(256) k_sortseg(
    const int* __restrict__ rp, int* __restrict__ col, int n)
{
    __shared__ int sbuf[8][1024];
    int lane = threadIdx.x & 31, w = threadIdx.x >> 5;
    int node = blockIdx.x * 8 + w;
    if (node >= n) return;
    int beg = rp[node], end = rp[node + 1];
    int d = end - beg;
    if (d <= 1) return;

    if (d <= 32) {
        int v = (lane < d) ? col[beg + lane] : 0x7fffffff;
#pragma unroll
        for (int k = 2; k <= 32; k <<= 1) {
#pragma unroll
            for (int j = k >> 1; j > 0; j >>= 1) {
                int other = __shfl_xor_sync(0xffffffffu, v, j);
                bool dirUp = ((lane & k) == 0);
                bool takeMin = (((lane & j) == 0) == dirUp);
                v = takeMin ? min(v, other) : max(v, other);
            }
        }
        if (lane < d) col[beg + lane] = v;
    } else if (d <= 1024) {
        int* s = sbuf[w];
        for (int i = lane; i < d; i += 32) s[i] = col[beg + i];
        __syncwarp();
        for (int ph = 0; ph < d; ph++) {
            int start = ph & 1;
            for (int i = start + 2 * lane; i + 1 < d; i += 64) {
                int a = s[i], b = s[i + 1];
                if (a > b) { s[i] = b; s[i + 1] = a; }
            }
            __syncwarp();
        }
        for (int i = lane; i < d; i += 32) col[beg + i] = s[i];
    } else {
        if (lane == 0) {
            for (int i = beg + 1; i < end; i++) {
                int key = col[i];
                int j = i - 1;
                while (j >= beg && col[j] > key) { col[j + 1] = col[j]; j--; }
                col[j + 1] = key;
            }
        }
    }
}

// =====================================================================
// Aggregation: warp per node, MLP=8 gather.
// =====================================================================
__device__ __forceinline__ void warp_agg(const float2* __restrict__ gin,
                                         const int* __restrict__ col,
                                         int beg, int end, int lane,
                                         float& ax, float& ay) {
    ax = 0.f; ay = 0.f;
    for (int e0 = beg; e0 < end; e0 += 32) {
        int idx = e0 + lane;
        int c = (idx < end) ? __ldg(&col[idx]) : 0;
        int cnt = min(32, end - e0);
        int j = 0;
        for (; j + 8 <= cnt; j += 8) {
            int s0 = __shfl_sync(0xffffffffu, c, j);
            int s1 = __shfl_sync(0xffffffffu, c, j + 1);
            int s2 = __shfl_sync(0xffffffffu, c, j + 2);
            int s3 = __shfl_sync(0xffffffffu, c, j + 3);
            int s4 = __shfl_sync(0xffffffffu, c, j + 4);
            int s5 = __shfl_sync(0xffffffffu, c, j + 5);
            int s6 = __shfl_sync(0xffffffffu, c, j + 6);
            int s7 = __shfl_sync(0xffffffffu, c, j + 7);
            float2 v0 = gin[s0 * 32 + lane];
            float2 v1 = gin[s1 * 32 + lane];
            float2 v2 = gin[s2 * 32 + lane];
            float2 v3 = gin[s3 * 32 + lane];
            float2 v4 = gin[s4 * 32 + lane];
            float2 v5 = gin[s5 * 32 + lane];
            float2 v6 = gin[s6 * 32 + lane];
            float2 v7 = gin[s7 * 32 + lane];
            ax += v0.x; ay += v0.y;
            ax += v1.x; ay += v1.y;
            ax += v2.x; ay += v2.y;
            ax += v3.x; ay += v3.y;
            ax += v4.x; ay += v4.y;
            ax += v5.x; ay += v5.y;
            ax += v6.x; ay += v6.y;
            ax += v7.x; ay += v7.y;
        }
        for (; j < cnt; j++) {
            int s = __shfl_sync(0xffffffffu, c, j);
            float2 v = gin[s * 32 + lane];
            ax += v.x; ay += v.y;
        }
    }
}

#define HT_STRIDE 10
__global__ void __launch_bounds__(256) k_agg_mm(
    const float2* __restrict__ gin, float2* __restrict__ gout,
    const int* __restrict__ rp, const int* __restrict__ col,
    const float* __restrict__ bias, const float* __restrict__ W, int n)
{
    __shared__ float Ws[D_HID * D_HID];
    __shared__ float hT[D_HID][HT_STRIDE];
    int tid = threadIdx.x;
    {
        const float4* s = (const float4*)W;
        float4* d = (float4*)Ws;
#pragma unroll
        for (int i = 0; i < 4; i++) d[tid + i * 256] = s[tid + i * 256];
    }
    int lane = tid & 31, w = tid >> 5;
    int node = blockIdx.x * 8 + w;
    if (node < n) {
        int beg = rp[node], end = rp[node + 1];
        float ax, ay;
        warp_agg(gin, col, beg, end, lane, ax, ay);
        float inv = 1.f / fmaxf((float)(end - beg), 1.f);
        float b0 = bias[2 * lane], b1v = bias[2 * lane + 1];
        hT[2 * lane][w]     = fmaxf(fmaf(ax, inv, b0), 0.f);
        hT[2 * lane + 1][w] = fmaxf(fmaf(ay, inv, b1v), 0.f);
    }
    __syncthreads();
    if (w < 4) {
        int n0 = blockIdx.x * 8 + 2 * w;
        if (n0 < n) {
            int n1 = n0 + 1;
            const float2* wsp = (const float2*)Ws;
            ull oXe = 0ull, oXo = 0ull, oYe = 0ull, oYo = 0ull;
#pragma unroll
            for (int k = 0; k < D_HID; k += 2) {
                ull h0 = *(const ull*)(&hT[k][2 * w]);
                ull h1 = *(const ull*)(&hT[k + 1][2 * w]);
                float2 w0 = wsp[k * 32 + lane];
                float2 w1 = wsp[(k + 1) * 32 + lane];
                ffma2(oXe, h0, dup2(w0.x));
                ffma2(oYe, h0, dup2(w0.y));
                ffma2(oXo, h1, dup2(w1.x));
                ffma2(oYo, h1, dup2(w1.y));
            }
            float2 xe = unpack2(oXe), xo = unpack2(oXo);
            float2 ye = unpack2(oYe), yo = unpack2(oYo);
            gout[n0 * 32 + lane] = make_float2(xe.x + xo.x, ye.x + yo.x);
            if (n1 < n)
                gout[n1 * 32 + lane] = make_float2(xe.y + xo.y, ye.y + yo.y);
        }
    }
}

__global__ void __launch_bounds__(256) k_agg_final(
    const float2* __restrict__ gin, float2* __restrict__ gout,
    const int* __restrict__ rp, const int* __restrict__ col,
    const float* __restrict__ bias, int n)
{
    int tid = threadIdx.x;
    int lane = tid & 31, w = tid >> 5;
    int node = blockIdx.x * 8 + w;
    if (node >= n) return;
    int beg = rp[node], end = rp[node + 1];
    float ax, ay;
    warp_agg(gin, col, beg, end, lane, ax, ay);
    float inv = 1.f / fmaxf((float)(end - beg), 1.f);
    float b0 = bias[2 * lane], b1v = bias[2 * lane + 1];
    float2 h;
    h.x = fmaxf(fmaf(ax, inv, b0), 0.f);
    h.y = fmaxf(fmaf(ay, inv, b1v), 0.f);
    gout[node * 32 + lane] = h;
}

// =====================================================================
// Deterministic two-pass batchnorm statistics
// =====================================================================
__global__ void __launch_bounds__(256) k_sum_mean(
    const float* __restrict__ h, int n, float* __restrict__ part)
{
    __shared__ float sb[4][64];
    int f = threadIdx.x & 63;
    int ty = threadIdx.x >> 6;
    float s = 0.f;
    for (int r = blockIdx.x * 4 + ty; r < n; r += gridDim.x * 4)
        s += h[(size_t)r * 64 + f];
    sb[ty][f] = s;
    __syncthreads();
    if (threadIdx.x < 64) {
        float t = ((sb[0][f] + sb[1][f]) + sb[2][f]) + sb[3][f];
        part[blockIdx.x * 64 + f] = t;
    }
}
__global__ void k_reduce_mean(const float* __restrict__ part, int nb, int n,
                              float* __restrict__ stats)
{
    int f = threadIdx.x;
    float s = 0.f;
    for (int b = 0; b < nb; b++) s += part[b * 64 + f];
    stats[f] = s / (float)n;
}
__global__ void __launch_bounds__(256) k_sum_var(
    const float* __restrict__ h, int n, const float* __restrict__ stats,
    float* __restrict__ part)
{
    __shared__ float sb[4][64];
    int f = threadIdx.x & 63;
    int ty = threadIdx.x >> 6;
    float mean = stats[f];
    float s = 0.f;
    for (int r = blockIdx.x * 4 + ty; r < n; r += gridDim.x * 4) {
        float d = h[(size_t)r * 64 + f] - mean;
        s = fmaf(d, d, s);
    }
    sb[ty][f] = s;
    __syncthreads();
    if (threadIdx.x < 64) {
        float t = ((sb[0][f] + sb[1][f]) + sb[2][f]) + sb[3][f];
        part[blockIdx.x * 64 + f] = t;
    }
}
__global__ void k_reduce_var(const float* __restrict__ part, int nb, int n,
                             const float* __restrict__ gamma,
                             const float* __restrict__ beta,
                             float* __restrict__ stats)
{
    int f = threadIdx.x;
    float s = 0.f;
    for (int b = 0; b < nb; b++) s += part[b * 64 + f];
    float var = s / (float)n;
    float mean = stats[f];
    float rstd = rsqrtf(var + 1e-5f);
    float sc = rstd * gamma[f];
    stats[128 + f] = sc;
    stats[192 + f] = beta[f] - mean * sc;
}

// =====================================================================
// Final head
// =====================================================================
__global__ void __launch_bounds__(256) k_final(
    const float2* __restrict__ h3, const float* __restrict__ stats,
    const float* __restrict__ W2, const float* __restrict__ b2,
    const float* __restrict__ W3, const float* __restrict__ b3,
    float* __restrict__ out, int n)
{
    __shared__ float W2s[D_HID * N_CLS];
    __shared__ float W3s[N_CLS * N_CLS];
    __shared__ float hb[8][D_HID];
    __shared__ float tb[8][N_CLS];
    int tid = threadIdx.x;
    {
        const float4* s2 = (const float4*)W2;
        float4* d2 = (float4*)W2s;
        d2[tid] = s2[tid];
        d2[tid + 256] = s2[tid + 256];
        ((float4*)W3s)[tid] = ((const float4*)W3)[tid];
    }
    __syncthreads();
    int lane = tid & 31, w = tid >> 5;
    int node = blockIdx.x * 8 + w;
    if (node >= n) return;
    float2 h = h3[node * 32 + lane];
    float s0 = stats[128 + 2 * lane], s1 = stats[128 + 2 * lane + 1];
    float t0 = stats[192 + 2 * lane], t1 = stats[192 + 2 * lane + 1];
    hb[w][2 * lane]     = fmaf(h.x, s0, t0);
    hb[w][2 * lane + 1] = fmaf(h.y, s1, t1);
    __syncwarp();
    float t = b2[lane];
#pragma unroll
    for (int k = 0; k < D_HID; k++) t = fmaf(hb[w][k], W2s[k * 32 + lane], t);
    t = fmaxf(t, 0.f);
    tb[w][lane] = t;
    __syncwarp();
    float o = b3[lane];
#pragma unroll
    for (int k = 0; k < N_CLS; k++) o = fmaf(tb[w][k], W3s[k * 32 + lane], o);
    out[(size_t)node * 32 + lane] = o;
}

// =====================================================================
// launch  (k_lin1_mma kept in the ncu-profiled slot #4)
// =====================================================================
extern "C" void kernel_launch(void* const* d_in, const int* in_sizes, int n_in,
                              void* d_out, int out_size) {
    const float* x     = (const float*)d_in[0];
    const float* W1    = (const float*)d_in[1];
    const float* b1    = (const float*)d_in[2];
    const float* Wc1   = (const float*)d_in[3];
    const float* bc1   = (const float*)d_in[4];
    const float* Wc2   = (const float*)d_in[5];
    const float* bc2   = (const float*)d_in[6];
    const float* Wc3   = (const float*)d_in[7];
    const float* bc3   = (const float*)d_in[8];
    const float* gamma = (const float*)d_in[9];
    const float* beta  = (const float*)d_in[10];
    const float* W2    = (const float*)d_in[11];
    const float* b2    = (const float*)d_in[12];
    const float* W3    = (const float*)d_in[13];
    const float* b3    = (const float*)d_in[14];
    const int*   ei    = (const int*)d_in[15];

    int n = in_sizes[0] / F_IN;
    int E = in_sizes[15] / 2;
    const int* src = ei;
    const int* dst = ei + E;

    float *bufA, *bufB, *stats, *part;
    uint32_t *wph, *wpl;
    int *deg, *incl, *bsum, *rp, *cur, *colb;
    cudaGetSymbolAddress((void**)&bufA, g_bufA);
    cudaGetSymbolAddress((void**)&bufB, g_bufB);
    cudaGetSymbolAddress((void**)&stats, g_stats);
    cudaGetSymbolAddress((void**)&part, g_part);
    cudaGetSymbolAddress((void**)&wph, g_Wp_hi);
    cudaGetSymbolAddress((void**)&wpl, g_Wp_lo);
    cudaGetSymbolAddress((void**)&deg, g_deg);
    cudaGetSymbolAddress((void**)&incl, g_incl);
    cudaGetSymbolAddress((void**)&bsum, g_bsum);
    cudaGetSymbolAddress((void**)&rp, g_rp);
    cudaGetSymbolAddress((void**)&cur, g_cur);
    cudaGetSymbolAddress((void**)&colb, g_col);

    cudaFuncSetAttribute(k_lin1_mma, cudaFuncAttributeMaxDynamicSharedMemorySize, MMA_SMEM);

    int NB = (n + 511) / 512;
    int ablocks = (n + 7) / 8;
    int mblocks = (n + 127) / 128;

    // prepW first; k_lin1_mma in launch slot #4 (ncu capture slot).
    k_prepW<<<64, 256>>>(W1, wph, wpl);
    k_zero_int<<<(n + 255) / 256, 256>>>(deg, n);
    k_hist<<<(E + 255) / 256, 256>>>(dst, E, deg);
    k_lin1_mma<<<mblocks, 512, MMA_SMEM>>>(x, wph, wpl, b1, Wc1, bufA, n);
    k_scan1<<<NB, 512>>>(deg, n, incl, bsum);
    k_scan1<<<1, 512>>>(bsum, NB, bsum, (int*)0);
    k_scan3<<<(n + 255) / 256, 256>>>(incl, bsum, deg, rp, cur, n);
    k_fill<<<(E + 255) / 256, 256>>>(src, dst, E, cur, colb);
    k_sortseg<<<ablocks, 256>>>(rp, colb, n);

    // conv1 (+Wc2 pre-applied), conv2 (+Wc3 pre-applied), conv3
    k_agg_mm<<<ablocks, 256>>>((const float2*)bufA, (float2*)bufB, rp, colb, bc1, Wc2, n);
    k_agg_mm<<<ablocks, 256>>>((const float2*)bufB, (float2*)bufA, rp, colb, bc2, Wc3, n);
    k_agg_final<<<ablocks, 256>>>((const float2*)bufA, (float2*)bufB, rp, colb, bc3, n);

    // deterministic two-pass batchnorm stats + head
    k_sum_mean<<<256, 256>>>(bufB, n, part);
    k_reduce_mean<<<1, 64>>>(part, 256, n, stats);
    k_sum_var<<<256, 256>>>(bufB, n, stats, part);
    k_reduce_var<<<1, 64>>>(part, 256, n, gamma, beta, stats);
    k_final<<<ablocks, 256>>>((const float2*)bufB, stats, W2, b2, W3, b3,
                              (float*)d_out, n);
}

// round 9
// speedup vs baseline: 1.4717x; 1.0081x over previous
#include <cuda_runtime.h>
#include <cuda_bf16.h>
#include <cstdint>

typedef unsigned long long ull;

#define F_IN   512
#define D_EMB  128
#define D_HID  64
#define N_CLS  32
#define MAXN   100000
#define MAXE   1600000

// ---------------- device scratch (no allocation allowed) ----------------
__device__ float g_bufA[MAXN * D_HID];
__device__ float g_bufB[MAXN * D_HID];
__device__ int   g_deg [MAXN + 2];
__device__ int   g_incl[MAXN + 2];
__device__ int   g_bsum[512];
__device__ int   g_rp  [MAXN + 2];
__device__ int   g_cur [MAXN + 2];
__device__ int   g_col [MAXE + 2];
__device__ float g_stats[256];
__device__ float g_part[256 * 64];
__device__ uint32_t g_Wp_hi[D_EMB * F_IN / 2];
__device__ uint32_t g_Wp_lo[D_EMB * F_IN / 2];

// ---------------- helpers ----------------
__device__ __forceinline__ ull dup2(float v) {
    ull r; asm("mov.b64 %0, {%1, %1};" : "=l"(r) : "f"(v)); return r;
}
__device__ __forceinline__ void ffma2(ull &acc, ull a, ull b) {
    asm("fma.rn.f32x2 %0, %1, %2, %0;" : "+l"(acc) : "l"(a), "l"(b));
}
__device__ __forceinline__ float2 unpack2(ull v) {
    float2 r; asm("mov.b64 {%0, %1}, %2;" : "=f"(r.x), "=f"(r.y) : "l"(v)); return r;
}
// pack two floats (k-even, k-odd) into bf16x2: a -> low half, b -> high half
__device__ __forceinline__ uint32_t pkbf(float a, float b) {
    uint32_t r; asm("cvt.rn.bf16x2.f32 %0, %1, %2;" : "=r"(r) : "f"(b), "f"(a));
    return r;
}
__device__ __forceinline__ float bf16f(float v) {
    return __bfloat162float(__float2bfloat16(v));
}

// portable tensor-core MMA: m16n8k16 bf16 (sm_80+; valid on compute_103)
#define MMA_BF16(c, a, b)                                                       \
    asm volatile(                                                               \
        "mma.sync.aligned.m16n8k16.row.col.f32.bf16.bf16.f32 "                  \
        "{%0,%1,%2,%3}, {%4,%5,%6,%7}, {%8,%9}, {%0,%1,%2,%3};"                 \
        : "+f"((c)[0]), "+f"((c)[1]), "+f"((c)[2]), "+f"((c)[3])                \
        : "r"((a).x), "r"((a).y), "r"((a).z), "r"((a).w),                       \
          "r"((b).x), "r"((b).y))

// =====================================================================
// k_prepW: W1[512][128] -> packed bf16x2 hi/lo, W1T layout [128][256 pairs]
// =====================================================================
__global__ void __launch_bounds__(256) k_prepW(
    const float* __restrict__ W1, uint32_t* __restrict__ hiP,
    uint32_t* __restrict__ loP)
{
    __shared__ float ts[32][33];
    int kt = blockIdx.x & 15, nt = blockIdx.x >> 4;
    int tx = threadIdx.x & 31, ty = threadIdx.x >> 5;   // ty 0..7
#pragma unroll
    for (int r = 0; r < 4; r++) {
        int k = kt * 32 + ty + r * 8;
        ts[ty + r * 8][tx] = W1[k * D_EMB + nt * 32 + tx];
    }
    __syncthreads();
#pragma unroll
    for (int it = 0; it < 2; it++) {
        int idx = threadIdx.x + it * 256;   // 0..511
        int nl = idx >> 4;                  // 0..31
        int q  = idx & 15;                  // pair 0..15
        float v0 = ts[2 * q][nl], v1 = ts[2 * q + 1][nl];
        uint32_t uh = pkbf(v0, v1);
        float h0 = bf16f(v0), h1 = bf16f(v1);
        uint32_t ul = pkbf(v0 - h0, v1 - h1);
        int nn = nt * 32 + nl;
        hiP[nn * 256 + kt * 16 + q] = uh;
        loP[nn * 256 + kt * 16 + q] = ul;
    }
}

// =====================================================================
// k_lin1_mma: g1 = relu(x @ W1 + b1) @ Wc1 via 3x BF16 mma.sync m16n8k16
// (unchanged from round 8)
// =====================================================================
#define ABLK 132
#define BBLK 68
#define AH_U 0
#define AL_U (16 * ABLK)
#define BH_U (2 * 16 * ABLK)
#define BL_U (2 * 16 * ABLK + 32 * BBLK)
#define ST_U (2 * 16 * ABLK + 2 * 32 * BBLK)   // 8576
#define MMA_SMEM ((2 * ST_U + 8192 + 128) * 4)
#define LIN1_HSS 132

__global__ void __launch_bounds__(512) k_lin1_mma(
    const float* __restrict__ x, const uint32_t* __restrict__ Whi,
    const uint32_t* __restrict__ Wlo, const float* __restrict__ b1,
    const float* __restrict__ Wc1, float* __restrict__ g1, int n)
{
    extern __shared__ float sm[];
    uint32_t* TL = (uint32_t*)sm;
    float* WcS   = sm + 2 * ST_U;
    float* b1s   = WcS + 8192;
    float* Hs    = sm;                       // epilogue overlay

    const int tid  = threadIdx.x;
    const int wid  = tid >> 5, lane = tid & 31;
    const int wm   = wid & 3, wn = wid >> 2;       // 4x4 warp grid
    const int row0 = blockIdx.x * 128;

    {
        const float4* s = (const float4*)Wc1;
        float4* d = (float4*)WcS;
#pragma unroll
        for (int i = 0; i < 4; i++) d[tid + i * 512] = s[tid + i * 512];
        if (tid < 128) b1s[tid] = b1[tid];
    }

    float c[2][4][4];
#pragma unroll
    for (int am = 0; am < 2; am++)
#pragma unroll
        for (int an = 0; an < 4; an++)
#pragma unroll
            for (int q = 0; q < 4; q++) c[am][an][q] = 0.f;

    float4 xa[2];
    uint2  wh[2], wl[2];

    auto FETCH = [&](int kc) {
#pragma unroll
        for (int it = 0; it < 2; it++) {
            int idx = tid + it * 512;
            int m = idx >> 3, j4 = idx & 7;
            bool v = (row0 + m) < n;
            xa[it] = v ? *(const float4*)(x + (size_t)(row0 + m) * F_IN + kc * 32 + j4 * 4)
                       : make_float4(0.f, 0.f, 0.f, 0.f);
            wh[it] = *(const uint2*)(Whi + (size_t)m * 256 + kc * 16 + 2 * j4);
            wl[it] = *(const uint2*)(Wlo + (size_t)m * 256 + kc * 16 + 2 * j4);
        }
    };
    auto STORE = [&](uint32_t* bs) {
#pragma unroll
        for (int it = 0; it < 2; it++) {
            int idx = tid + it * 512;
            int m = idx >> 3, j4 = idx & 7;
            int ks = j4 >> 2, jj = j4 & 3;
            int tig0 = (jj & 1) * 2, ph = jj >> 1;
            float4 a = xa[it];
            uint32_t uh0 = pkbf(a.x, a.y), uh1 = pkbf(a.z, a.w);
            float h0 = bf16f(a.x), h1 = bf16f(a.y);
            float h2 = bf16f(a.z), h3 = bf16f(a.w);
            uint32_t ul0 = pkbf(a.x - h0, a.y - h1);
            uint32_t ul1 = pkbf(a.z - h2, a.w - h3);
            int gid = m & 7, rh = (m >> 3) & 1, mt = m >> 4;
            int s0 = ((mt * 2 + ks)) * ABLK + 16 * gid + 4 * tig0 + rh + 2 * ph;
            bs[AH_U + s0]     = uh0;
            bs[AH_U + s0 + 4] = uh1;
            bs[AL_U + s0]     = ul0;
            bs[AL_U + s0 + 4] = ul1;
            int t0 = ((m >> 3) * 2 + ks) * BBLK + 8 * (m & 7) + 2 * tig0 + ph;
            bs[BH_U + t0]     = wh[it].x;
            bs[BH_U + t0 + 2] = wh[it].y;
            bs[BL_U + t0]     = wl[it].x;
            bs[BL_U + t0 + 2] = wl[it].y;
        }
    };

    FETCH(0);
    STORE(TL);
    __syncthreads();

    for (int kc = 0; kc < 16; kc++) {
        if (kc + 1 < 16) FETCH(kc + 1);
        const uint32_t* st = TL + (kc & 1) * ST_U;
#pragma unroll
        for (int ks = 0; ks < 2; ks++) {
            uint4 ahf[2], alf[2];
#pragma unroll
            for (int am = 0; am < 2; am++) {
                int bA = ((wm * 2 + am) * 2 + ks) * ABLK + lane * 4;
                ahf[am] = *(const uint4*)(st + AH_U + bA);
                alf[am] = *(const uint4*)(st + AL_U + bA);
            }
#pragma unroll
            for (int an = 0; an < 4; an++) {
                int bB = ((wn * 4 + an) * 2 + ks) * BBLK + lane * 2;
                uint2 bhf = *(const uint2*)(st + BH_U + bB);
                uint2 blf = *(const uint2*)(st + BL_U + bB);
#pragma unroll
                for (int am = 0; am < 2; am++) {
                    MMA_BF16(c[am][an], ahf[am], bhf);
                    MMA_BF16(c[am][an], ahf[am], blf);
                    MMA_BF16(c[am][an], alf[am], bhf);
                }
            }
        }
        if (kc + 1 < 16) STORE(TL + ((kc + 1) & 1) * ST_U);
        __syncthreads();
    }
    __syncthreads();

    const int gid = lane >> 2, tig = lane & 3;
#pragma unroll
    for (int am = 0; am < 2; am++) {
        int r0 = wm * 32 + am * 16 + gid;
#pragma unroll
        for (int an = 0; an < 4; an++) {
            int col = wn * 32 + an * 8 + 2 * tig;
            float bb0 = b1s[col], bb1 = b1s[col + 1];
            float2 lo2 = make_float2(fmaxf(c[am][an][0] + bb0, 0.f),
                                     fmaxf(c[am][an][1] + bb1, 0.f));
            float2 hi2 = make_float2(fmaxf(c[am][an][2] + bb0, 0.f),
                                     fmaxf(c[am][an][3] + bb1, 0.f));
            *(float2*)(Hs + r0 * LIN1_HSS + col)       = lo2;
            *(float2*)(Hs + (r0 + 8) * LIN1_HSS + col) = hi2;
        }
    }
    __syncthreads();

    {
        int tx = tid & 15, ty = tid >> 4;
        ull o[4][2];
#pragma unroll
        for (int r = 0; r < 4; r++) { o[r][0] = 0ull; o[r][1] = 0ull; }
#pragma unroll 8
        for (int em = 0; em < D_EMB; em++) {
            double2 wp = *(const double2*)(WcS + em * D_HID + tx * 4);
            ull w0 = __double_as_longlong(wp.x);
            ull w1 = __double_as_longlong(wp.y);
#pragma unroll
            for (int r = 0; r < 4; r++) {
                ull hd = dup2(Hs[(ty * 4 + r) * LIN1_HSS + em]);
                ffma2(o[r][0], hd, w0);
                ffma2(o[r][1], hd, w1);
            }
        }
#pragma unroll
        for (int r = 0; r < 4; r++) {
            int m = ty * 4 + r;
            if (row0 + m < n) {
                float2 e = unpack2(o[r][0]), f = unpack2(o[r][1]);
                *(float4*)(g1 + (size_t)(row0 + m) * D_HID + tx * 4) =
                    make_float4(e.x, e.y, f.x, f.y);
            }
        }
    }
}

// =====================================================================
// CSR build
// =====================================================================
__global__ void k_zero_int(int* p, int n) {
    int i = blockIdx.x * blockDim.x + threadIdx.x;
    if (i < n) p[i] = 0;
}
__global__ void k_hist(const int* __restrict__ dst, int E, int* __restrict__ deg) {
    int e = blockIdx.x * blockDim.x + threadIdx.x;
    if (e < E) atomicAdd(&deg[dst[e]], 1);
}
__global__ void k_scan1(const int* __restrict__ in, int n,
                        int* __restrict__ incl, int* __restrict__ bsum) {
    __shared__ int s[512];
    int i = blockIdx.x * 512 + threadIdx.x;
    s[threadIdx.x] = (i < n) ? in[i] : 0;
    __syncthreads();
#pragma unroll
    for (int off = 1; off < 512; off <<= 1) {
        int t = (threadIdx.x >= off) ? s[threadIdx.x - off] : 0;
        __syncthreads();
        s[threadIdx.x] += t;
        __syncthreads();
    }
    if (i < n) incl[i] = s[threadIdx.x];
    if (bsum && threadIdx.x == 511) bsum[blockIdx.x] = s[511];
}
__global__ void k_scan3(const int* __restrict__ incl, const int* __restrict__ bsum,
                        const int* __restrict__ deg, int* __restrict__ rp,
                        int* __restrict__ cur, int n) {
    int i = blockIdx.x * blockDim.x + threadIdx.x;
    if (i >= n) return;
    int b = i >> 9;
    int off = (b > 0) ? bsum[b - 1] : 0;
    int v = incl[i] + off;
    rp[i + 1] = v;
    cur[i] = v - deg[i];
    if (i == 0) rp[0] = 0;
}
__global__ void k_fill(const int* __restrict__ src, const int* __restrict__ dst,
                       int E, int* __restrict__ cur, int* __restrict__ col) {
    int e = blockIdx.x * blockDim.x + threadIdx.x;
    if (e >= E) return;
    int pos = atomicAdd(&cur[dst[e]], 1);
    col[pos] = src[e];
}

// =====================================================================
// Canonicalize CSR segment order (determinism)
// =====================================================================
__global__ void __launch_bounds__(256) k_sortseg(
    const int* __restrict__ rp, int* __restrict__ col, int n)
{
    __shared__ int sbuf[8][1024];
    int lane = threadIdx.x & 31, w = threadIdx.x >> 5;
    int node = blockIdx.x * 8 + w;
    if (node >= n) return;
    int beg = rp[node], end = rp[node + 1];
    int d = end - beg;
    if (d <= 1) return;

    if (d <= 32) {
        int v = (lane < d) ? col[beg + lane] : 0x7fffffff;
#pragma unroll
        for (int k = 2; k <= 32; k <<= 1) {
#pragma unroll
            for (int j = k >> 1; j > 0; j >>= 1) {
                int other = __shfl_xor_sync(0xffffffffu, v, j);
                bool dirUp = ((lane & k) == 0);
                bool takeMin = (((lane & j) == 0) == dirUp);
                v = takeMin ? min(v, other) : max(v, other);
            }
        }
        if (lane < d) col[beg + lane] = v;
    } else if (d <= 1024) {
        int* s = sbuf[w];
        for (int i = lane; i < d; i += 32) s[i] = col[beg + i];
        __syncwarp();
        for (int ph = 0; ph < d; ph++) {
            int start = ph & 1;
            for (int i = start + 2 * lane; i + 1 < d; i += 64) {
                int a = s[i], b = s[i + 1];
                if (a > b) { s[i] = b; s[i + 1] = a; }
            }
            __syncwarp();
        }
        for (int i = lane; i < d; i += 32) col[beg + i] = s[i];
    } else {
        if (lane == 0) {
            for (int i = beg + 1; i < end; i++) {
                int key = col[i];
                int j = i - 1;
                while (j >= beg && col[j] > key) { col[j + 1] = col[j]; j--; }
                col[j + 1] = key;
            }
        }
    }
}

// =====================================================================
// Aggregation: HALF-WARP (16 lanes) per node, float4 gathers, MLP=8.
// Neighbor order = sorted CSR order, summed sequentially per feature:
// numerically identical to the previous warp-per-node version.
// =====================================================================
__device__ __forceinline__ float4 hw_agg(const float4* __restrict__ gin,
                                         const int* __restrict__ col,
                                         int beg, int end, int hl,
                                         unsigned hmask) {
    float4 acc = make_float4(0.f, 0.f, 0.f, 0.f);
    for (int e0 = beg; e0 < end; e0 += 16) {
        int idx = e0 + hl;
        int c = (idx < end) ? __ldg(&col[idx]) : 0;
        int cnt = min(16, end - e0);
        int j = 0;
        for (; j + 8 <= cnt; j += 8) {
            int s0 = __shfl_sync(hmask, c, j,     16);
            int s1 = __shfl_sync(hmask, c, j + 1, 16);
            int s2 = __shfl_sync(hmask, c, j + 2, 16);
            int s3 = __shfl_sync(hmask, c, j + 3, 16);
            int s4 = __shfl_sync(hmask, c, j + 4, 16);
            int s5 = __shfl_sync(hmask, c, j + 5, 16);
            int s6 = __shfl_sync(hmask, c, j + 6, 16);
            int s7 = __shfl_sync(hmask, c, j + 7, 16);
            float4 v0 = gin[(size_t)s0 * 16 + hl];
            float4 v1 = gin[(size_t)s1 * 16 + hl];
            float4 v2 = gin[(size_t)s2 * 16 + hl];
            float4 v3 = gin[(size_t)s3 * 16 + hl];
            float4 v4 = gin[(size_t)s4 * 16 + hl];
            float4 v5 = gin[(size_t)s5 * 16 + hl];
            float4 v6 = gin[(size_t)s6 * 16 + hl];
            float4 v7 = gin[(size_t)s7 * 16 + hl];
            acc.x += v0.x; acc.y += v0.y; acc.z += v0.z; acc.w += v0.w;
            acc.x += v1.x; acc.y += v1.y; acc.z += v1.z; acc.w += v1.w;
            acc.x += v2.x; acc.y += v2.y; acc.z += v2.z; acc.w += v2.w;
            acc.x += v3.x; acc.y += v3.y; acc.z += v3.z; acc.w += v3.w;
            acc.x += v4.x; acc.y += v4.y; acc.z += v4.z; acc.w += v4.w;
            acc.x += v5.x; acc.y += v5.y; acc.z += v5.z; acc.w += v5.w;
            acc.x += v6.x; acc.y += v6.y; acc.z += v6.z; acc.w += v6.w;
            acc.x += v7.x; acc.y += v7.y; acc.z += v7.z; acc.w += v7.w;
        }
        for (; j < cnt; j++) {
            int s = __shfl_sync(hmask, c, j, 16);
            float4 v = gin[(size_t)s * 16 + hl];
            acc.x += v.x; acc.y += v.y; acc.z += v.z; acc.w += v.w;
        }
    }
    return acc;
}

// agg + fused 64x64 MM: 16 nodes/block; all 8 warps compute MM (2 nodes each)
#define HT_STRIDE 18
__global__ void __launch_bounds__(256) k_agg_mm(
    const float4* __restrict__ gin, float2* __restrict__ gout,
    const int* __restrict__ rp, const int* __restrict__ col,
    const float* __restrict__ bias, const float* __restrict__ W, int n)
{
    __shared__ float Ws[D_HID * D_HID];
    __shared__ float hT[D_HID][HT_STRIDE];
    int tid = threadIdx.x;
    {
        const float4* s = (const float4*)W;
        float4* d = (float4*)Ws;
#pragma unroll
        for (int i = 0; i < 4; i++) d[tid + i * 256] = s[tid + i * 256];
    }
    int hl = tid & 15, half = tid >> 4;            // half 0..15
    unsigned hmask = (half & 1) ? 0xFFFF0000u : 0x0000FFFFu;
    int node = blockIdx.x * 16 + half;
    if (node < n) {
        int beg = rp[node], end = rp[node + 1];
        float4 acc = hw_agg(gin, col, beg, end, hl, hmask);
        float inv = 1.f / fmaxf((float)(end - beg), 1.f);
        float4 b4 = ((const float4*)bias)[hl];
        hT[4 * hl + 0][half] = fmaxf(fmaf(acc.x, inv, b4.x), 0.f);
        hT[4 * hl + 1][half] = fmaxf(fmaf(acc.y, inv, b4.y), 0.f);
        hT[4 * hl + 2][half] = fmaxf(fmaf(acc.z, inv, b4.z), 0.f);
        hT[4 * hl + 3][half] = fmaxf(fmaf(acc.w, inv, b4.w), 0.f);
    }
    __syncthreads();
    {
        int lane = tid & 31, w = tid >> 5;         // 8 warps, 2 nodes each
        int n0 = blockIdx.x * 16 + 2 * w;
        if (n0 < n) {
            int n1 = n0 + 1;
            const float2* wsp = (const float2*)Ws;
            ull oXe = 0ull, oXo = 0ull, oYe = 0ull, oYo = 0ull;
#pragma unroll
            for (int k = 0; k < D_HID; k += 2) {
                ull h0 = *(const ull*)(&hT[k][2 * w]);
                ull h1 = *(const ull*)(&hT[k + 1][2 * w]);
                float2 w0 = wsp[k * 32 + lane];
                float2 w1 = wsp[(k + 1) * 32 + lane];
                ffma2(oXe, h0, dup2(w0.x));
                ffma2(oYe, h0, dup2(w0.y));
                ffma2(oXo, h1, dup2(w1.x));
                ffma2(oYo, h1, dup2(w1.y));
            }
            float2 xe = unpack2(oXe), xo = unpack2(oXo);
            float2 ye = unpack2(oYe), yo = unpack2(oYo);
            gout[n0 * 32 + lane] = make_float2(xe.x + xo.x, ye.x + yo.x);
            if (n1 < n)
                gout[n1 * 32 + lane] = make_float2(xe.y + xo.y, ye.y + yo.y);
        }
    }
}

__global__ void __launch_bounds__(256) k_agg_final(
    const float4* __restrict__ gin, float4* __restrict__ gout,
    const int* __restrict__ rp, const int* __restrict__ col,
    const float* __restrict__ bias, int n)
{
    int tid = threadIdx.x;
    int hl = tid & 15, half = tid >> 4;
    unsigned hmask = (half & 1) ? 0xFFFF0000u : 0x0000FFFFu;
    int node = blockIdx.x * 16 + half;
    if (node >= n) return;
    int beg = rp[node], end = rp[node + 1];
    float4 acc = hw_agg(gin, col, beg, end, hl, hmask);
    float inv = 1.f / fmaxf((float)(end - beg), 1.f);
    float4 b4 = ((const float4*)bias)[hl];
    float4 h;
    h.x = fmaxf(fmaf(acc.x, inv, b4.x), 0.f);
    h.y = fmaxf(fmaf(acc.y, inv, b4.y), 0.f);
    h.z = fmaxf(fmaf(acc.z, inv, b4.z), 0.f);
    h.w = fmaxf(fmaf(acc.w, inv, b4.w), 0.f);
    gout[(size_t)node * 16 + hl] = h;
}

// =====================================================================
// Deterministic two-pass batchnorm statistics
// =====================================================================
__global__ void __launch_bounds__(256) k_sum_mean(
    const float* __restrict__ h, int n, float* __restrict__ part)
{
    __shared__ float sb[4][64];
    int f = threadIdx.x & 63;
    int ty = threadIdx.x >> 6;
    float s = 0.f;
    for (int r = blockIdx.x * 4 + ty; r < n; r += gridDim.x * 4)
        s += h[(size_t)r * 64 + f];
    sb[ty][f] = s;
    __syncthreads();
    if (threadIdx.x < 64) {
        float t = ((sb[0][f] + sb[1][f]) + sb[2][f]) + sb[3][f];
        part[blockIdx.x * 64 + f] = t;
    }
}
__global__ void k_reduce_mean(const float* __restrict__ part, int nb, int n,
                              float* __restrict__ stats)
{
    int f = threadIdx.x;
    float s = 0.f;
    for (int b = 0; b < nb; b++) s += part[b * 64 + f];
    stats[f] = s / (float)n;
}
__global__ void __launch_bounds__(256) k_sum_var(
    const float* __restrict__ h, int n, const float* __restrict__ stats,
    float* __restrict__ part)
{
    __shared__ float sb[4][64];
    int f = threadIdx.x & 63;
    int ty = threadIdx.x >> 6;
    float mean = stats[f];
    float s = 0.f;
    for (int r = blockIdx.x * 4 + ty; r < n; r += gridDim.x * 4) {
        float d = h[(size_t)r * 64 + f] - mean;
        s = fmaf(d, d, s);
    }
    sb[ty][f] = s;
    __syncthreads();
    if (threadIdx.x < 64) {
        float t = ((sb[0][f] + sb[1][f]) + sb[2][f]) + sb[3][f];
        part[blockIdx.x * 64 + f] = t;
    }
}
__global__ void k_reduce_var(const float* __restrict__ part, int nb, int n,
                             const float* __restrict__ gamma,
                             const float* __restrict__ beta,
                             float* __restrict__ stats)
{
    int f = threadIdx.x;
    float s = 0.f;
    for (int b = 0; b < nb; b++) s += part[b * 64 + f];
    float var = s / (float)n;
    float mean = stats[f];
    float rstd = rsqrtf(var + 1e-5f);
    float sc = rstd * gamma[f];
    stats[128 + f] = sc;
    stats[192 + f] = beta[f] - mean * sc;
}

// =====================================================================
// Final head
// =====================================================================
__global__ void __launch_bounds__(256) k_final(
    const float2* __restrict__ h3, const float* __restrict__ stats,
    const float* __restrict__ W2, const float* __restrict__ b2,
    const float* __restrict__ W3, const float* __restrict__ b3,
    float* __restrict__ out, int n)
{
    __shared__ float W2s[D_HID * N_CLS];
    __shared__ float W3s[N_CLS * N_CLS];
    __shared__ float hb[8][D_HID];
    __shared__ float tb[8][N_CLS];
    int tid = threadIdx.x;
    {
        const float4* s2 = (const float4*)W2;
        float4* d2 = (float4*)W2s;
        d2[tid] = s2[tid];
        d2[tid + 256] = s2[tid + 256];
        ((float4*)W3s)[tid] = ((const float4*)W3)[tid];
    }
    __syncthreads();
    int lane = tid & 31, w = tid >> 5;
    int node = blockIdx.x * 8 + w;
    if (node >= n) return;
    float2 h = h3[node * 32 + lane];
    float s0 = stats[128 + 2 * lane], s1 = stats[128 + 2 * lane + 1];
    float t0 = stats[192 + 2 * lane], t1 = stats[192 + 2 * lane + 1];
    hb[w][2 * lane]     = fmaf(h.x, s0, t0);
    hb[w][2 * lane + 1] = fmaf(h.y, s1, t1);
    __syncwarp();
    float t = b2[lane];
#pragma unroll
    for (int k = 0; k < D_HID; k++) t = fmaf(hb[w][k], W2s[k * 32 + lane], t);
    t = fmaxf(t, 0.f);
    tb[w][lane] = t;
    __syncwarp();
    float o = b3[lane];
#pragma unroll
    for (int k = 0; k < N_CLS; k++) o = fmaf(tb[w][k], W3s[k * 32 + lane], o);
    out[(size_t)node * 32 + lane] = o;
}

// =====================================================================
// launch  (k_lin1_mma kept in the ncu-profiled slot #4)
// =====================================================================
extern "C" void kernel_launch(void* const* d_in, const int* in_sizes, int n_in,
                              void* d_out, int out_size) {
    const float* x     = (const float*)d_in[0];
    const float* W1    = (const float*)d_in[1];
    const float* b1    = (const float*)d_in[2];
    const float* Wc1   = (const float*)d_in[3];
    const float* bc1   = (const float*)d_in[4];
    const float* Wc2   = (const float*)d_in[5];
    const float* bc2   = (const float*)d_in[6];
    const float* Wc3   = (const float*)d_in[7];
    const float* bc3   = (const float*)d_in[8];
    const float* gamma = (const float*)d_in[9];
    const float* beta  = (const float*)d_in[10];
    const float* W2    = (const float*)d_in[11];
    const float* b2    = (const float*)d_in[12];
    const float* W3    = (const float*)d_in[13];
    const float* b3    = (const float*)d_in[14];
    const int*   ei    = (const int*)d_in[15];

    int n = in_sizes[0] / F_IN;
    int E = in_sizes[15] / 2;
    const int* src = ei;
    const int* dst = ei + E;

    float *bufA, *bufB, *stats, *part;
    uint32_t *wph, *wpl;
    int *deg, *incl, *bsum, *rp, *cur, *colb;
    cudaGetSymbolAddress((void**)&bufA, g_bufA);
    cudaGetSymbolAddress((void**)&bufB, g_bufB);
    cudaGetSymbolAddress((void**)&stats, g_stats);
    cudaGetSymbolAddress((void**)&part, g_part);
    cudaGetSymbolAddress((void**)&wph, g_Wp_hi);
    cudaGetSymbolAddress((void**)&wpl, g_Wp_lo);
    cudaGetSymbolAddress((void**)&deg, g_deg);
    cudaGetSymbolAddress((void**)&incl, g_incl);
    cudaGetSymbolAddress((void**)&bsum, g_bsum);
    cudaGetSymbolAddress((void**)&rp, g_rp);
    cudaGetSymbolAddress((void**)&cur, g_cur);
    cudaGetSymbolAddress((void**)&colb, g_col);

    cudaFuncSetAttribute(k_lin1_mma, cudaFuncAttributeMaxDynamicSharedMemorySize, MMA_SMEM);

    int NB = (n + 511) / 512;
    int ablocks8  = (n + 7) / 8;
    int ablocks16 = (n + 15) / 16;
    int mblocks = (n + 127) / 128;

    // prepW first; k_lin1_mma in launch slot #4 (ncu capture slot).
    k_prepW<<<64, 256>>>(W1, wph, wpl);
    k_zero_int<<<(n + 255) / 256, 256>>>(deg, n);
    k_hist<<<(E + 255) / 256, 256>>>(dst, E, deg);
    k_lin1_mma<<<mblocks, 512, MMA_SMEM>>>(x, wph, wpl, b1, Wc1, bufA, n);
    k_scan1<<<NB, 512>>>(deg, n, incl, bsum);
    k_scan1<<<1, 512>>>(bsum, NB, bsum, (int*)0);
    k_scan3<<<(n + 255) / 256, 256>>>(incl, bsum, deg, rp, cur, n);
    k_fill<<<(E + 255) / 256, 256>>>(src, dst, E, cur, colb);
    k_sortseg<<<ablocks8, 256>>>(rp, colb, n);

    // conv1 (+Wc2 pre-applied), conv2 (+Wc3 pre-applied), conv3
    k_agg_mm<<<ablocks16, 256>>>((const float4*)bufA, (float2*)bufB, rp, colb, bc1, Wc2, n);
    k_agg_mm<<<ablocks16, 256>>>((const float4*)bufB, (float2*)bufA, rp, colb, bc2, Wc3, n);
    k_agg_final<<<ablocks16, 256>>>((const float4*)bufA, (float4*)bufB, rp, colb, bc3, n);

    // deterministic two-pass batchnorm stats + head
    k_sum_mean<<<256, 256>>>(bufB, n, part);
    k_reduce_mean<<<1, 64>>>(part, 256, n, stats);
    k_sum_var<<<256, 256>>>(bufB, n, stats, part);
    k_reduce_var<<<1, 64>>>(part, 256, n, gamma, beta, stats);
    k_final<<<ablocks8, 256>>>((const float2*)bufB, stats, W2, b2, W3, b3,
                               (float*)d_out, n);
}